// round 1
// baseline (speedup 1.0000x reference)
#include <cuda_runtime.h>
#include <cstddef>

// Problem constants
#define BSZ   2
#define NSEQ  2048
#define DIN   2048
#define DOUT  2048
#define NH    16
#define NG    4
#define HD    128
#define MROWS (BSZ * NSEQ)   // 4096

// ---------------- scratch (no allocations allowed) ----------------
__device__ float g_q[MROWS * DOUT];          // [b,n,h,d]
__device__ float g_k[MROWS * NG * HD];       // [b,n,g,d]
__device__ float g_v[MROWS * NG * HD];       // [b,n,g,d]
__device__ float g_ctx[MROWS * DOUT];        // [b,n,h,d]

// ---------------- fp32 SGEMM: C[M,N] = A[M,K] @ B[K,N] (+bias) ----------------
// BM=128, BN=128, BK=8, TM=8, TN=8, 256 threads
__global__ __launch_bounds__(256) void sgemm_kernel(
    const float* __restrict__ A, const float* __restrict__ B,
    float* __restrict__ C, const float* __restrict__ bias,
    int M, int N, int K)
{
    __shared__ float As[8][128];
    __shared__ float Bs[8][128];

    const int tid  = threadIdx.x;
    const int row0 = blockIdx.y * 128;
    const int col0 = blockIdx.x * 128;

    const int aRow = tid >> 1;            // 0..127
    const int aCol = (tid & 1) * 4;       // 0 or 4
    const int bRow = tid >> 5;            // 0..7
    const int bCol = (tid & 31) * 4;      // 0..124

    const int tRow = (tid >> 4) * 8;      // 0..120
    const int tCol = (tid & 15) * 8;      // 0..120

    float acc[8][8];
    #pragma unroll
    for (int i = 0; i < 8; i++)
        #pragma unroll
        for (int j = 0; j < 8; j++) acc[i][j] = 0.f;

    for (int k0 = 0; k0 < K; k0 += 8) {
        float4 a = *(const float4*)(A + (size_t)(row0 + aRow) * K + k0 + aCol);
        As[aCol + 0][aRow] = a.x;
        As[aCol + 1][aRow] = a.y;
        As[aCol + 2][aRow] = a.z;
        As[aCol + 3][aRow] = a.w;
        float4 b = *(const float4*)(B + (size_t)(k0 + bRow) * N + col0 + bCol);
        *(float4*)&Bs[bRow][bCol] = b;
        __syncthreads();

        #pragma unroll
        for (int kk = 0; kk < 8; kk++) {
            float regM[8], regN[8];
            #pragma unroll
            for (int i = 0; i < 8; i++) regM[i] = As[kk][tRow + i];
            #pragma unroll
            for (int j = 0; j < 8; j++) regN[j] = Bs[kk][tCol + j];
            #pragma unroll
            for (int i = 0; i < 8; i++)
                #pragma unroll
                for (int j = 0; j < 8; j++)
                    acc[i][j] = fmaf(regM[i], regN[j], acc[i][j]);
        }
        __syncthreads();
    }

    #pragma unroll
    for (int i = 0; i < 8; i++) {
        float* crow = C + (size_t)(row0 + tRow + i) * N + col0 + tCol;
        if (bias != nullptr) {
            #pragma unroll
            for (int j = 0; j < 8; j++) acc[i][j] += bias[col0 + tCol + j];
        }
        float4 o0 = make_float4(acc[i][0], acc[i][1], acc[i][2], acc[i][3]);
        float4 o1 = make_float4(acc[i][4], acc[i][5], acc[i][6], acc[i][7]);
        *(float4*)(crow + 0) = o0;
        *(float4*)(crow + 4) = o1;
    }
}

// ---------------- causal GQA flash attention (fp32) ----------------
// 1 warp per query row, 8 rows/CTA, K/V tiled 32 keys x 128 in smem.
__global__ __launch_bounds__(256) void attn_kernel(
    const float* __restrict__ Q,   // [b,n,h,d]
    const float* __restrict__ K,   // [b,n,g,d]
    const float* __restrict__ V,   // [b,n,g,d]
    float* __restrict__ O)         // [b,n,h,d]
{
    __shared__ float sK[32][HD];
    __shared__ float sV[32][HD];

    const int lane = threadIdx.x & 31;
    const int warp = threadIdx.x >> 5;     // 0..7
    const int b    = blockIdx.z;
    const int h    = blockIdx.y;           // 0..15
    const int g    = h >> 2;               // h / REP
    const int qi   = blockIdx.x * 8 + warp;
    const int qmax = blockIdx.x * 8 + 7;

    const float scale = 0.08838834764831845f;  // 1/sqrt(128)

    float4 q4 = *(const float4*)(Q + ((size_t)(b * NSEQ + qi) * NH + h) * HD + lane * 4);

    float  m = -1e30f;
    float  l = 0.f;
    float4 acc = make_float4(0.f, 0.f, 0.f, 0.f);

    const int nblocks = (qmax >> 5) + 1;
    for (int kb = 0; kb < nblocks; kb++) {
        const int j0 = kb * 32;
        __syncthreads();
        // cooperative load of 32 keys x 128 (K and V): 1024 float4 each, 256 thr
        #pragma unroll
        for (int t = 0; t < 4; t++) {
            int idx = threadIdx.x + t * 256;        // 0..1023
            int j   = idx >> 5;                     // key row 0..31
            int c   = (idx & 31) * 4;               // col 0..124
            size_t base = ((size_t)(b * NSEQ + j0 + j) * NG + g) * HD + c;
            *(float4*)&sK[j][c] = *(const float4*)(K + base);
            *(float4*)&sV[j][c] = *(const float4*)(V + base);
        }
        __syncthreads();

        const int jend = min(32, qi - j0 + 1);      // causal bound (may be <=0)
        for (int j = 0; j < jend; j++) {
            float4 k4 = *(const float4*)&sK[j][lane * 4];
            float p = q4.x * k4.x + q4.y * k4.y + q4.z * k4.z + q4.w * k4.w;
            p += __shfl_xor_sync(0xFFFFFFFFu, p, 16);
            p += __shfl_xor_sync(0xFFFFFFFFu, p, 8);
            p += __shfl_xor_sync(0xFFFFFFFFu, p, 4);
            p += __shfl_xor_sync(0xFFFFFFFFu, p, 2);
            p += __shfl_xor_sync(0xFFFFFFFFu, p, 1);
            float s = p * scale;
            float4 v4 = *(const float4*)&sV[j][lane * 4];
            if (s > m) {
                float alpha = __expf(m - s);
                m = s;
                l = l * alpha + 1.f;
                acc.x = fmaf(acc.x, alpha, v4.x);
                acc.y = fmaf(acc.y, alpha, v4.y);
                acc.z = fmaf(acc.z, alpha, v4.z);
                acc.w = fmaf(acc.w, alpha, v4.w);
            } else {
                float pe = __expf(s - m);
                l += pe;
                acc.x = fmaf(pe, v4.x, acc.x);
                acc.y = fmaf(pe, v4.y, acc.y);
                acc.z = fmaf(pe, v4.z, acc.z);
                acc.w = fmaf(pe, v4.w, acc.w);
            }
        }
    }

    const float inv = 1.f / l;
    float4 o = make_float4(acc.x * inv, acc.y * inv, acc.z * inv, acc.w * inv);
    *(float4*)(O + ((size_t)(b * NSEQ + qi) * NH + h) * HD + lane * 4) = o;
}

// ---------------- launch ----------------
extern "C" void kernel_launch(void* const* d_in, const int* in_sizes, int n_in,
                              void* d_out, int out_size)
{
    const float* x  = (const float*)d_in[0];
    const float* Wq = (const float*)d_in[1];
    const float* Wk = (const float*)d_in[2];
    const float* Wv = (const float*)d_in[3];
    const float* Wo = (const float*)d_in[4];
    const float* bo = (const float*)d_in[5];
    float* out = (float*)d_out;

    float *pq, *pk, *pv, *pctx;
    cudaGetSymbolAddress((void**)&pq,   g_q);
    cudaGetSymbolAddress((void**)&pk,   g_k);
    cudaGetSymbolAddress((void**)&pv,   g_v);
    cudaGetSymbolAddress((void**)&pctx, g_ctx);

    dim3 blk(256);

    // Q = x @ Wq : [4096,2048] x [2048,2048]
    sgemm_kernel<<<dim3(DOUT / 128, MROWS / 128), blk>>>(x, Wq, pq, nullptr, MROWS, DOUT, DIN);
    // K = x @ Wk : [4096,2048] x [2048,512]
    sgemm_kernel<<<dim3((NG * HD) / 128, MROWS / 128), blk>>>(x, Wk, pk, nullptr, MROWS, NG * HD, DIN);
    // V = x @ Wv
    sgemm_kernel<<<dim3((NG * HD) / 128, MROWS / 128), blk>>>(x, Wv, pv, nullptr, MROWS, NG * HD, DIN);

    // attention: grid (N/8 row-blocks, H heads, B)
    attn_kernel<<<dim3(NSEQ / 8, NH, BSZ), blk>>>(pq, pk, pv, pctx);

    // out = ctx @ Wo + bo
    sgemm_kernel<<<dim3(DOUT / 128, MROWS / 128), blk>>>(pctx, Wo, out, bo, MROWS, DOUT, DOUT);
}

// round 2
// speedup vs baseline: 1.6548x; 1.6548x over previous
#include <cuda_runtime.h>
#include <cstddef>

// Problem constants
#define BSZ   2
#define NSEQ  2048
#define DIN   2048
#define DOUT  2048
#define NH    16
#define NG    4
#define HD    128
#define MROWS (BSZ * NSEQ)   // 4096

// Attention tiling
#define BQ    64      // query rows per CTA
#define BKEY  64      // key rows per block
#define ROWP  132     // padded row stride (floats) for Q/K/V tiles: 16B aligned, bank-spread
#define SP    65      // padded row stride for score tile

// ---------------- scratch (no allocations allowed) ----------------
__device__ float g_q[MROWS * DOUT];          // [b,n,h,d]
__device__ float g_k[MROWS * NG * HD];       // [b,n,g,d]
__device__ float g_v[MROWS * NG * HD];       // [b,n,g,d]
__device__ float g_ctx[MROWS * DOUT];        // [b,n,h,d]

// ---------------- fp32 SGEMM: C[M,N] = A[M,K] @ B[K,N] (+bias) ----------------
__global__ __launch_bounds__(256) void sgemm_kernel(
    const float* __restrict__ A, const float* __restrict__ B,
    float* __restrict__ C, const float* __restrict__ bias,
    int M, int N, int K)
{
    __shared__ float As[8][128];
    __shared__ float Bs[8][128];

    const int tid  = threadIdx.x;
    const int row0 = blockIdx.y * 128;
    const int col0 = blockIdx.x * 128;

    const int aRow = tid >> 1;
    const int aCol = (tid & 1) * 4;
    const int bRow = tid >> 5;
    const int bCol = (tid & 31) * 4;

    const int tRow = (tid >> 4) * 8;
    const int tCol = (tid & 15) * 8;

    float acc[8][8];
    #pragma unroll
    for (int i = 0; i < 8; i++)
        #pragma unroll
        for (int j = 0; j < 8; j++) acc[i][j] = 0.f;

    for (int k0 = 0; k0 < K; k0 += 8) {
        float4 a = *(const float4*)(A + (size_t)(row0 + aRow) * K + k0 + aCol);
        As[aCol + 0][aRow] = a.x;
        As[aCol + 1][aRow] = a.y;
        As[aCol + 2][aRow] = a.z;
        As[aCol + 3][aRow] = a.w;
        float4 b = *(const float4*)(B + (size_t)(k0 + bRow) * N + col0 + bCol);
        *(float4*)&Bs[bRow][bCol] = b;
        __syncthreads();

        #pragma unroll
        for (int kk = 0; kk < 8; kk++) {
            float regM[8], regN[8];
            #pragma unroll
            for (int i = 0; i < 8; i++) regM[i] = As[kk][tRow + i];
            #pragma unroll
            for (int j = 0; j < 8; j++) regN[j] = Bs[kk][tCol + j];
            #pragma unroll
            for (int i = 0; i < 8; i++)
                #pragma unroll
                for (int j = 0; j < 8; j++)
                    acc[i][j] = fmaf(regM[i], regN[j], acc[i][j]);
        }
        __syncthreads();
    }

    #pragma unroll
    for (int i = 0; i < 8; i++) {
        float* crow = C + (size_t)(row0 + tRow + i) * N + col0 + tCol;
        if (bias != nullptr) {
            #pragma unroll
            for (int j = 0; j < 8; j++) acc[i][j] += bias[col0 + tCol + j];
        }
        float4 o0 = make_float4(acc[i][0], acc[i][1], acc[i][2], acc[i][3]);
        float4 o1 = make_float4(acc[i][4], acc[i][5], acc[i][6], acc[i][7]);
        *(float4*)(crow + 0) = o0;
        *(float4*)(crow + 4) = o1;
    }
}

// ---------------- register-tiled causal GQA flash attention (fp32) ----------------
// CTA: one (b,h), 64 query rows. Key blocks of 64.
// Stage 1 (score): S[64][64] = Q tile @ K tile^T, 4q x 4k register tiles.
// Stage 2: 64-thread online row softmax.
// Stage 3 (PV):   O[64][128] += P @ V, 4q x 8d register tiles.
struct AttnSmem {
    float q[BQ][ROWP];     // 33792 B
    float k[BKEY][ROWP];   // 33792 B
    float v[BKEY][ROWP];   // 33792 B
    float s[BQ][SP];       // 16640 B
    float m[BQ];
    float l[BQ];
    float alpha[BQ];
};
// total = 118784 + 768 = ~116.7 KB dynamic smem

extern __shared__ char attn_smem_raw[];

__global__ __launch_bounds__(256) void attn2_kernel(
    const float* __restrict__ Q,   // [b,n,h,d]
    const float* __restrict__ Kg,  // [b,n,g,d]
    const float* __restrict__ Vg,  // [b,n,g,d]
    float* __restrict__ O)         // [b,n,h,d]
{
    AttnSmem& sm = *reinterpret_cast<AttnSmem*>(attn_smem_raw);
    const int t  = threadIdx.x;
    const int b  = blockIdx.z;
    const int h  = blockIdx.y;
    const int g  = h >> 2;
    const int qb = gridDim.x - 1 - blockIdx.x;   // big CTAs launch first
    const int q0 = qb * BQ;

    const float scale = 0.08838834764831845f;    // 1/sqrt(128)

    const int tq = t >> 4;     // 0..15 : 4 query rows tq*4..tq*4+3
    const int tk = t & 15;     // 0..15 : score cols tk+16j ; PV d-group

    // --- load Q tile (64 x 128), coalesced, natural layout ---
    #pragma unroll
    for (int it = 0; it < 8; it++) {
        int idx = t + it * 256;          // 0..2047
        int q   = idx >> 5;              // 0..63
        int c   = (idx & 31) * 4;        // 0..124
        float4 a = *(const float4*)(Q + ((size_t)(b * NSEQ + q0 + q) * NH + h) * HD + c);
        *(float4*)&sm.q[q][c] = a;
    }
    if (t < BQ) { sm.m[t] = -1e30f; sm.l[t] = 0.f; }

    float o[4][8];
    #pragma unroll
    for (int i = 0; i < 4; i++)
        #pragma unroll
        for (int j = 0; j < 8; j++) o[i][j] = 0.f;

    for (int kb = 0; kb <= qb; kb++) {
        __syncthreads();
        // --- load K,V block (64 x 128 each), coalesced ---
        #pragma unroll
        for (int it = 0; it < 8; it++) {
            int idx = t + it * 256;
            int k   = idx >> 5;
            int c   = (idx & 31) * 4;
            size_t base = ((size_t)(b * NSEQ + kb * BKEY + k) * NG + g) * HD + c;
            *(float4*)&sm.k[k][c] = *(const float4*)(Kg + base);
            *(float4*)&sm.v[k][c] = *(const float4*)(Vg + base);
        }
        __syncthreads();

        // --- score: S[tq*4+i][tk+16*j] ---
        {
            float acc[4][4];
            #pragma unroll
            for (int i = 0; i < 4; i++)
                #pragma unroll
                for (int j = 0; j < 4; j++) acc[i][j] = 0.f;

            #pragma unroll 4
            for (int d4 = 0; d4 < 32; d4++) {
                float4 qv[4], kv[4];
                #pragma unroll
                for (int i = 0; i < 4; i++)
                    qv[i] = *(const float4*)&sm.q[tq * 4 + i][d4 * 4];
                #pragma unroll
                for (int j = 0; j < 4; j++)
                    kv[j] = *(const float4*)&sm.k[tk + 16 * j][d4 * 4];
                #pragma unroll
                for (int i = 0; i < 4; i++)
                    #pragma unroll
                    for (int j = 0; j < 4; j++) {
                        acc[i][j] = fmaf(qv[i].x, kv[j].x, acc[i][j]);
                        acc[i][j] = fmaf(qv[i].y, kv[j].y, acc[i][j]);
                        acc[i][j] = fmaf(qv[i].z, kv[j].z, acc[i][j]);
                        acc[i][j] = fmaf(qv[i].w, kv[j].w, acc[i][j]);
                    }
            }
            const bool diag = (kb == qb);
            #pragma unroll
            for (int i = 0; i < 4; i++) {
                int ql = tq * 4 + i;
                #pragma unroll
                for (int j = 0; j < 4; j++) {
                    int kl = tk + 16 * j;
                    float s = acc[i][j] * scale;
                    if (diag && kl > ql) s = -1e30f;
                    sm.s[ql][kl] = s;
                }
            }
        }
        __syncthreads();

        // --- online softmax, one thread per query row ---
        if (t < BQ) {
            float mold = sm.m[t];
            float mb = -1e30f;
            #pragma unroll 8
            for (int k = 0; k < BKEY; k++) mb = fmaxf(mb, sm.s[t][k]);
            float mnew  = fmaxf(mold, mb);
            float alpha = __expf(mold - mnew);
            float sum = 0.f;
            #pragma unroll 8
            for (int k = 0; k < BKEY; k++) {
                float p = __expf(sm.s[t][k] - mnew);
                sm.s[t][k] = p;
                sum += p;
            }
            sm.m[t] = mnew;
            sm.l[t] = sm.l[t] * alpha + sum;
            sm.alpha[t] = alpha;
        }
        __syncthreads();

        // --- PV: O[tq*4+i][d] += P @ V, d in {tk*4..tk*4+3} U {64+tk*4..} ---
        {
            float al[4];
            #pragma unroll
            for (int i = 0; i < 4; i++) al[i] = sm.alpha[tq * 4 + i];
            #pragma unroll
            for (int i = 0; i < 4; i++)
                #pragma unroll
                for (int j = 0; j < 8; j++) o[i][j] *= al[i];

            #pragma unroll 4
            for (int k = 0; k < BKEY; k++) {
                float4 v0 = *(const float4*)&sm.v[k][tk * 4];
                float4 v1 = *(const float4*)&sm.v[k][64 + tk * 4];
                float p0 = sm.s[tq * 4 + 0][k];
                float p1 = sm.s[tq * 4 + 1][k];
                float p2 = sm.s[tq * 4 + 2][k];
                float p3 = sm.s[tq * 4 + 3][k];
                o[0][0] = fmaf(p0, v0.x, o[0][0]); o[0][1] = fmaf(p0, v0.y, o[0][1]);
                o[0][2] = fmaf(p0, v0.z, o[0][2]); o[0][3] = fmaf(p0, v0.w, o[0][3]);
                o[0][4] = fmaf(p0, v1.x, o[0][4]); o[0][5] = fmaf(p0, v1.y, o[0][5]);
                o[0][6] = fmaf(p0, v1.z, o[0][6]); o[0][7] = fmaf(p0, v1.w, o[0][7]);
                o[1][0] = fmaf(p1, v0.x, o[1][0]); o[1][1] = fmaf(p1, v0.y, o[1][1]);
                o[1][2] = fmaf(p1, v0.z, o[1][2]); o[1][3] = fmaf(p1, v0.w, o[1][3]);
                o[1][4] = fmaf(p1, v1.x, o[1][4]); o[1][5] = fmaf(p1, v1.y, o[1][5]);
                o[1][6] = fmaf(p1, v1.z, o[1][6]); o[1][7] = fmaf(p1, v1.w, o[1][7]);
                o[2][0] = fmaf(p2, v0.x, o[2][0]); o[2][1] = fmaf(p2, v0.y, o[2][1]);
                o[2][2] = fmaf(p2, v0.z, o[2][2]); o[2][3] = fmaf(p2, v0.w, o[2][3]);
                o[2][4] = fmaf(p2, v1.x, o[2][4]); o[2][5] = fmaf(p2, v1.y, o[2][5]);
                o[2][6] = fmaf(p2, v1.z, o[2][6]); o[2][7] = fmaf(p2, v1.w, o[2][7]);
                o[3][0] = fmaf(p3, v0.x, o[3][0]); o[3][1] = fmaf(p3, v0.y, o[3][1]);
                o[3][2] = fmaf(p3, v0.z, o[3][2]); o[3][3] = fmaf(p3, v0.w, o[3][3]);
                o[3][4] = fmaf(p3, v1.x, o[3][4]); o[3][5] = fmaf(p3, v1.y, o[3][5]);
                o[3][6] = fmaf(p3, v1.z, o[3][6]); o[3][7] = fmaf(p3, v1.w, o[3][7]);
            }
        }
    }

    // --- epilogue: normalize and store ---
    #pragma unroll
    for (int i = 0; i < 4; i++) {
        int q = tq * 4 + i;
        float inv = 1.f / sm.l[q];
        float* orow = O + ((size_t)(b * NSEQ + q0 + q) * NH + h) * HD;
        float4 w0 = make_float4(o[i][0] * inv, o[i][1] * inv, o[i][2] * inv, o[i][3] * inv);
        float4 w1 = make_float4(o[i][4] * inv, o[i][5] * inv, o[i][6] * inv, o[i][7] * inv);
        *(float4*)(orow + tk * 4)      = w0;
        *(float4*)(orow + 64 + tk * 4) = w1;
    }
}

// ---------------- launch ----------------
extern "C" void kernel_launch(void* const* d_in, const int* in_sizes, int n_in,
                              void* d_out, int out_size)
{
    const float* x  = (const float*)d_in[0];
    const float* Wq = (const float*)d_in[1];
    const float* Wk = (const float*)d_in[2];
    const float* Wv = (const float*)d_in[3];
    const float* Wo = (const float*)d_in[4];
    const float* bo = (const float*)d_in[5];
    float* out = (float*)d_out;

    float *pq, *pk, *pv, *pctx;
    cudaGetSymbolAddress((void**)&pq,   g_q);
    cudaGetSymbolAddress((void**)&pk,   g_k);
    cudaGetSymbolAddress((void**)&pv,   g_v);
    cudaGetSymbolAddress((void**)&pctx, g_ctx);

    const int smem_bytes = (int)sizeof(AttnSmem);
    cudaFuncSetAttribute(attn2_kernel, cudaFuncAttributeMaxDynamicSharedMemorySize, smem_bytes);

    dim3 blk(256);

    sgemm_kernel<<<dim3(DOUT / 128, MROWS / 128), blk>>>(x, Wq, pq, nullptr, MROWS, DOUT, DIN);
    sgemm_kernel<<<dim3((NG * HD) / 128, MROWS / 128), blk>>>(x, Wk, pk, nullptr, MROWS, NG * HD, DIN);
    sgemm_kernel<<<dim3((NG * HD) / 128, MROWS / 128), blk>>>(x, Wv, pv, nullptr, MROWS, NG * HD, DIN);

    attn2_kernel<<<dim3(NSEQ / BQ, NH, BSZ), blk, smem_bytes>>>(pq, pk, pv, pctx);

    sgemm_kernel<<<dim3(DOUT / 128, MROWS / 128), blk>>>(pctx, Wo, out, bo, MROWS, DOUT, DOUT);
}

// round 4
// speedup vs baseline: 2.9911x; 1.8075x over previous
#include <cuda_runtime.h>
#include <cuda_bf16.h>
#include <cstdint>
#include <cstddef>

// Problem constants
#define BSZ   2
#define NSEQ  2048
#define DIN   2048
#define DOUT  2048
#define NH    16
#define NG    4
#define HD    128
#define MROWS (BSZ * NSEQ)   // 4096
#define KVDIM (NG * HD)      // 512

// Attention tiling
#define BQ    64
#define BKEY  64
#define ROWP  132
#define SP    65

// ---------------- scratch (no allocations allowed) ----------------
__device__ float g_q[MROWS * DOUT];
__device__ float g_k[MROWS * KVDIM];
__device__ float g_v[MROWS * KVDIM];
__device__ float g_ctx[MROWS * DOUT];

__device__ __align__(16) __nv_bfloat16 g_xh[MROWS * DIN];
__device__ __align__(16) __nv_bfloat16 g_xl[MROWS * DIN];
__device__ __align__(16) __nv_bfloat16 g_ctxh[MROWS * DOUT];
__device__ __align__(16) __nv_bfloat16 g_ctxl[MROWS * DOUT];
__device__ __align__(16) __nv_bfloat16 g_wqth[DOUT * DIN];   // Wq^T [N,K]
__device__ __align__(16) __nv_bfloat16 g_wqtl[DOUT * DIN];
__device__ __align__(16) __nv_bfloat16 g_wkth[KVDIM * DIN];
__device__ __align__(16) __nv_bfloat16 g_wktl[KVDIM * DIN];
__device__ __align__(16) __nv_bfloat16 g_wvth[KVDIM * DIN];
__device__ __align__(16) __nv_bfloat16 g_wvtl[KVDIM * DIN];
__device__ __align__(16) __nv_bfloat16 g_woth[DOUT * DOUT];
__device__ __align__(16) __nv_bfloat16 g_wotl[DOUT * DOUT];

// ---------------- helpers ----------------
__device__ __forceinline__ uint32_t smem_u32(const void* p) {
    uint32_t a;
    asm("{ .reg .u64 t; cvta.to.shared.u64 t, %1; cvt.u32.u64 %0, t; }" : "=r"(a) : "l"(p));
    return a;
}

__device__ __forceinline__ void cp_async16(uint32_t saddr, const void* gaddr) {
    asm volatile("cp.async.cg.shared.global [%0], [%1], 16;" :: "r"(saddr), "l"(gaddr));
}
#define CP_COMMIT() asm volatile("cp.async.commit_group;" ::: "memory")
#define CP_WAIT(n)  asm volatile("cp.async.wait_group %0;" :: "n"(n) : "memory")

__device__ __forceinline__ void ldm_x4(uint32_t& r0, uint32_t& r1, uint32_t& r2, uint32_t& r3,
                                       uint32_t addr) {
    asm volatile("ldmatrix.sync.aligned.m8n8.x4.shared.b16 {%0, %1, %2, %3}, [%4];"
                 : "=r"(r0), "=r"(r1), "=r"(r2), "=r"(r3) : "r"(addr));
}

__device__ __forceinline__ void mma_bf16(float* d, const uint32_t* a, const uint32_t* b) {
    asm volatile(
        "mma.sync.aligned.m16n8k16.row.col.f32.bf16.bf16.f32 "
        "{%0, %1, %2, %3}, {%4, %5, %6, %7}, {%8, %9}, {%0, %1, %2, %3};"
        : "+f"(d[0]), "+f"(d[1]), "+f"(d[2]), "+f"(d[3])
        : "r"(a[0]), "r"(a[1]), "r"(a[2]), "r"(a[3]), "r"(b[0]), "r"(b[1]));
}

// ---------------- split / transpose conversion kernels ----------------
__global__ __launch_bounds__(256) void split_fp32_kernel(
    const float* __restrict__ in, __nv_bfloat16* __restrict__ hi,
    __nv_bfloat16* __restrict__ lo, int n4)
{
    int i = blockIdx.x * 256 + threadIdx.x;
    if (i >= n4) return;
    float4 v = ((const float4*)in)[i];
    __nv_bfloat16 h0 = __float2bfloat16(v.x);
    __nv_bfloat16 h1 = __float2bfloat16(v.y);
    __nv_bfloat16 h2 = __float2bfloat16(v.z);
    __nv_bfloat16 h3 = __float2bfloat16(v.w);
    __nv_bfloat16 l0 = __float2bfloat16(v.x - __bfloat162float(h0));
    __nv_bfloat16 l1 = __float2bfloat16(v.y - __bfloat162float(h1));
    __nv_bfloat16 l2 = __float2bfloat16(v.z - __bfloat162float(h2));
    __nv_bfloat16 l3 = __float2bfloat16(v.w - __bfloat162float(h3));
    __nv_bfloat162 ph0; ph0.x = h0; ph0.y = h1;
    __nv_bfloat162 ph1; ph1.x = h2; ph1.y = h3;
    __nv_bfloat162 pl0; pl0.x = l0; pl0.y = l1;
    __nv_bfloat162 pl1; pl1.x = l2; pl1.y = l3;
    ((__nv_bfloat162*)hi)[2 * i]     = ph0;
    ((__nv_bfloat162*)hi)[2 * i + 1] = ph1;
    ((__nv_bfloat162*)lo)[2 * i]     = pl0;
    ((__nv_bfloat162*)lo)[2 * i + 1] = pl1;
}

// W[K,N] fp32 -> T[N,K] bf16 hi/lo
__global__ __launch_bounds__(256) void transpose_split_kernel(
    const float* __restrict__ W, __nv_bfloat16* __restrict__ Th,
    __nv_bfloat16* __restrict__ Tl, int K, int N)
{
    __shared__ float tile[32][33];
    int k0 = blockIdx.y * 32, n0 = blockIdx.x * 32;
    int tx = threadIdx.x & 31, ty = threadIdx.x >> 5;   // 32 x 8
    #pragma unroll
    for (int r = ty; r < 32; r += 8)
        tile[r][tx] = W[(size_t)(k0 + r) * N + n0 + tx];
    __syncthreads();
    #pragma unroll
    for (int r = ty; r < 32; r += 8) {
        float v = tile[tx][r];
        __nv_bfloat16 h = __float2bfloat16(v);
        __nv_bfloat16 l = __float2bfloat16(v - __bfloat162float(h));
        size_t o = (size_t)(n0 + r) * K + k0 + tx;
        Th[o] = h;
        Tl[o] = l;
    }
}

// ---------------- HMMA split-bf16 GEMM: C[M,N] = A[M,K] @ BT[N,K]^T ----------------
// CTA 128x128, BK=32, 8 warps (2 along M x 4 along N), warp tile 64x32.
// smem rows padded to 40 bf16 (80 B) -> ldmatrix conflict-free.
#define GBK       32
#define LDROW     40                       // bf16 elements per smem row (80 B)
#define TILE_B    (128 * LDROW * 2)        // 10240 B per tensor tile
#define STAGE_B   (4 * TILE_B)             // 40960 B per stage
#define GEMM_SMEM (2 * STAGE_B)            // 81920 B

__global__ __launch_bounds__(256, 1) void mma_gemm_kernel(
    const __nv_bfloat16* __restrict__ Ah, const __nv_bfloat16* __restrict__ Al,
    const __nv_bfloat16* __restrict__ Bh, const __nv_bfloat16* __restrict__ Bl,
    float* __restrict__ C, const float* __restrict__ bias, int N, int K)
{
    extern __shared__ char smem[];
    const uint32_t sb = smem_u32(smem);
    const int tid  = threadIdx.x;
    const int wid  = tid >> 5;
    const int lane = tid & 31;
    const int row0 = blockIdx.y * 128;
    const int col0 = blockIdx.x * 128;
    const int wm   = (wid & 1) * 64;       // warp M offset in tile
    const int wn   = (wid >> 1) * 32;      // warp N offset in tile

    const __nv_bfloat16* gsrc[4] = {Ah, Al, Bh, Bl};

    float acc[4][4][4];                    // [mi][ni][reg]
    #pragma unroll
    for (int i = 0; i < 4; i++)
        #pragma unroll
        for (int j = 0; j < 4; j++)
            #pragma unroll
            for (int r = 0; r < 4; r++) acc[i][j][r] = 0.f;

    const int nch = K / GBK;

    // stage loader: 2048 x 16B chunks, 8 per thread
    auto load_stage = [&](int ch, int stage) {
        const int k0 = ch * GBK;
        const uint32_t sbase = sb + stage * STAGE_B;
        #pragma unroll
        for (int t = 0; t < 8; t++) {
            int idx = tid + t * 256;            // 0..2047
            int tensor = idx >> 9;              // 0..3
            int rem = idx & 511;
            int r = rem >> 2;                   // 0..127
            int c = rem & 3;                    // 16B chunk
            int grow = (tensor < 2) ? (row0 + r) : (col0 + r);
            const __nv_bfloat16* gp = gsrc[tensor] + (size_t)grow * K + k0 + c * 8;
            uint32_t sa = sbase + tensor * TILE_B + (r * LDROW + c * 8) * 2;
            cp_async16(sa, gp);
        }
    };

    load_stage(0, 0);
    CP_COMMIT();

    for (int ch = 0; ch < nch; ch++) {
        if (ch + 1 < nch) {
            load_stage(ch + 1, (ch + 1) & 1);
            CP_COMMIT();
            CP_WAIT(1);
        } else {
            CP_WAIT(0);
        }
        __syncthreads();

        const uint32_t sbase = sb + (ch & 1) * STAGE_B;
        const uint32_t a_hi = sbase + 0 * TILE_B;
        const uint32_t a_lo = sbase + 1 * TILE_B;
        const uint32_t b_hi = sbase + 2 * TILE_B;
        const uint32_t b_lo = sbase + 3 * TILE_B;

        #pragma unroll
        for (int ks = 0; ks < 2; ks++) {
            const uint32_t kb = ks * 32;       // byte offset of k16 chunk
            // A fragments (hi & lo): 4 m16 tiles each
            uint32_t fah[4][4], fal[4][4];
            #pragma unroll
            for (int mi = 0; mi < 4; mi++) {
                uint32_t roff = (uint32_t)(wm + mi * 16 + (lane & 15)) * (LDROW * 2)
                              + kb + (lane >> 4) * 16;
                ldm_x4(fah[mi][0], fah[mi][1], fah[mi][2], fah[mi][3], a_hi + roff);
                ldm_x4(fal[mi][0], fal[mi][1], fal[mi][2], fal[mi][3], a_lo + roff);
            }
            // B fragments (hi & lo): 4 n8 tiles each, loaded 2 per ldmatrix.x4
            uint32_t fbh[4][2], fbl[4][2];
            #pragma unroll
            for (int p = 0; p < 2; p++) {
                uint32_t roff = (uint32_t)(wn + p * 16 + (lane >> 4) * 8 + (lane & 7)) * (LDROW * 2)
                              + kb + ((lane >> 3) & 1) * 16;
                uint32_t r0, r1, r2, r3;
                ldm_x4(r0, r1, r2, r3, b_hi + roff);
                fbh[2 * p][0] = r0; fbh[2 * p][1] = r1;
                fbh[2 * p + 1][0] = r2; fbh[2 * p + 1][1] = r3;
                ldm_x4(r0, r1, r2, r3, b_lo + roff);
                fbl[2 * p][0] = r0; fbl[2 * p][1] = r1;
                fbl[2 * p + 1][0] = r2; fbl[2 * p + 1][1] = r3;
            }
            // 3 passes into one accumulator
            #pragma unroll
            for (int mi = 0; mi < 4; mi++)
                #pragma unroll
                for (int ni = 0; ni < 4; ni++) {
                    mma_bf16(acc[mi][ni], fah[mi], fbh[ni]);
                    mma_bf16(acc[mi][ni], fah[mi], fbl[ni]);
                    mma_bf16(acc[mi][ni], fal[mi], fbh[ni]);
                }
        }
        __syncthreads();
    }

    // epilogue: direct float2 stores
    const int qrow = lane >> 2;
    const int qcol = (lane & 3) * 2;
    #pragma unroll
    for (int mi = 0; mi < 4; mi++) {
        #pragma unroll
        for (int ni = 0; ni < 4; ni++) {
            int r = row0 + wm + mi * 16 + qrow;
            int c = col0 + wn + ni * 8 + qcol;
            float b0 = 0.f, b1 = 0.f;
            if (bias != nullptr) { b0 = bias[c]; b1 = bias[c + 1]; }
            float2 v0 = make_float2(acc[mi][ni][0] + b0, acc[mi][ni][1] + b1);
            float2 v1 = make_float2(acc[mi][ni][2] + b0, acc[mi][ni][3] + b1);
            *(float2*)(C + (size_t)r * N + c)       = v0;
            *(float2*)(C + (size_t)(r + 8) * N + c) = v1;
        }
    }
}

// ---------------- register-tiled causal GQA flash attention (fp32) ----------------
struct AttnSmem {
    float q[BQ][ROWP];
    float k[BKEY][ROWP];
    float v[BKEY][ROWP];
    float s[BQ][SP];
    float m[BQ];
    float l[BQ];
    float alpha[BQ];
};

extern __shared__ char attn_smem_raw[];

__global__ __launch_bounds__(256) void attn2_kernel(
    const float* __restrict__ Q,
    const float* __restrict__ Kg,
    const float* __restrict__ Vg,
    float* __restrict__ O)
{
    AttnSmem& sm = *reinterpret_cast<AttnSmem*>(attn_smem_raw);
    const int t  = threadIdx.x;
    const int b  = blockIdx.z;
    const int h  = blockIdx.y;
    const int g  = h >> 2;
    const int qb = gridDim.x - 1 - blockIdx.x;
    const int q0 = qb * BQ;

    const float scale = 0.08838834764831845f;

    const int tq = t >> 4;
    const int tk = t & 15;

    #pragma unroll
    for (int it = 0; it < 8; it++) {
        int idx = t + it * 256;
        int q   = idx >> 5;
        int c   = (idx & 31) * 4;
        float4 a = *(const float4*)(Q + ((size_t)(b * NSEQ + q0 + q) * NH + h) * HD + c);
        *(float4*)&sm.q[q][c] = a;
    }
    if (t < BQ) { sm.m[t] = -1e30f; sm.l[t] = 0.f; }

    float o[4][8];
    #pragma unroll
    for (int i = 0; i < 4; i++)
        #pragma unroll
        for (int j = 0; j < 8; j++) o[i][j] = 0.f;

    for (int kb = 0; kb <= qb; kb++) {
        __syncthreads();
        #pragma unroll
        for (int it = 0; it < 8; it++) {
            int idx = t + it * 256;
            int k   = idx >> 5;
            int c   = (idx & 31) * 4;
            size_t base = ((size_t)(b * NSEQ + kb * BKEY + k) * NG + g) * HD + c;
            *(float4*)&sm.k[k][c] = *(const float4*)(Kg + base);
            *(float4*)&sm.v[k][c] = *(const float4*)(Vg + base);
        }
        __syncthreads();

        {
            float acc[4][4];
            #pragma unroll
            for (int i = 0; i < 4; i++)
                #pragma unroll
                for (int j = 0; j < 4; j++) acc[i][j] = 0.f;

            #pragma unroll 4
            for (int d4 = 0; d4 < 32; d4++) {
                float4 qv[4], kv[4];
                #pragma unroll
                for (int i = 0; i < 4; i++)
                    qv[i] = *(const float4*)&sm.q[tq * 4 + i][d4 * 4];
                #pragma unroll
                for (int j = 0; j < 4; j++)
                    kv[j] = *(const float4*)&sm.k[tk + 16 * j][d4 * 4];
                #pragma unroll
                for (int i = 0; i < 4; i++)
                    #pragma unroll
                    for (int j = 0; j < 4; j++) {
                        acc[i][j] = fmaf(qv[i].x, kv[j].x, acc[i][j]);
                        acc[i][j] = fmaf(qv[i].y, kv[j].y, acc[i][j]);
                        acc[i][j] = fmaf(qv[i].z, kv[j].z, acc[i][j]);
                        acc[i][j] = fmaf(qv[i].w, kv[j].w, acc[i][j]);
                    }
            }
            const bool diag = (kb == qb);
            #pragma unroll
            for (int i = 0; i < 4; i++) {
                int ql = tq * 4 + i;
                #pragma unroll
                for (int j = 0; j < 4; j++) {
                    int kl = tk + 16 * j;
                    float s = acc[i][j] * scale;
                    if (diag && kl > ql) s = -1e30f;
                    sm.s[ql][kl] = s;
                }
            }
        }
        __syncthreads();

        if (t < BQ) {
            float mold = sm.m[t];
            float mb = -1e30f;
            #pragma unroll 8
            for (int k = 0; k < BKEY; k++) mb = fmaxf(mb, sm.s[t][k]);
            float mnew  = fmaxf(mold, mb);
            float alpha = __expf(mold - mnew);
            float sum = 0.f;
            #pragma unroll 8
            for (int k = 0; k < BKEY; k++) {
                float p = __expf(sm.s[t][k] - mnew);
                sm.s[t][k] = p;
                sum += p;
            }
            sm.m[t] = mnew;
            sm.l[t] = sm.l[t] * alpha + sum;
            sm.alpha[t] = alpha;
        }
        __syncthreads();

        {
            float al[4];
            #pragma unroll
            for (int i = 0; i < 4; i++) al[i] = sm.alpha[tq * 4 + i];
            #pragma unroll
            for (int i = 0; i < 4; i++)
                #pragma unroll
                for (int j = 0; j < 8; j++) o[i][j] *= al[i];

            #pragma unroll 4
            for (int k = 0; k < BKEY; k++) {
                float4 v0 = *(const float4*)&sm.v[k][tk * 4];
                float4 v1 = *(const float4*)&sm.v[k][64 + tk * 4];
                float p0 = sm.s[tq * 4 + 0][k];
                float p1 = sm.s[tq * 4 + 1][k];
                float p2 = sm.s[tq * 4 + 2][k];
                float p3 = sm.s[tq * 4 + 3][k];
                o[0][0] = fmaf(p0, v0.x, o[0][0]); o[0][1] = fmaf(p0, v0.y, o[0][1]);
                o[0][2] = fmaf(p0, v0.z, o[0][2]); o[0][3] = fmaf(p0, v0.w, o[0][3]);
                o[0][4] = fmaf(p0, v1.x, o[0][4]); o[0][5] = fmaf(p0, v1.y, o[0][5]);
                o[0][6] = fmaf(p0, v1.z, o[0][6]); o[0][7] = fmaf(p0, v1.w, o[0][7]);
                o[1][0] = fmaf(p1, v0.x, o[1][0]); o[1][1] = fmaf(p1, v0.y, o[1][1]);
                o[1][2] = fmaf(p1, v0.z, o[1][2]); o[1][3] = fmaf(p1, v0.w, o[1][3]);
                o[1][4] = fmaf(p1, v1.x, o[1][4]); o[1][5] = fmaf(p1, v1.y, o[1][5]);
                o[1][6] = fmaf(p1, v1.z, o[1][6]); o[1][7] = fmaf(p1, v1.w, o[1][7]);
                o[2][0] = fmaf(p2, v0.x, o[2][0]); o[2][1] = fmaf(p2, v0.y, o[2][1]);
                o[2][2] = fmaf(p2, v0.z, o[2][2]); o[2][3] = fmaf(p2, v0.w, o[2][3]);
                o[2][4] = fmaf(p2, v1.x, o[2][4]); o[2][5] = fmaf(p2, v1.y, o[2][5]);
                o[2][6] = fmaf(p2, v1.z, o[2][6]); o[2][7] = fmaf(p2, v1.w, o[2][7]);
                o[3][0] = fmaf(p3, v0.x, o[3][0]); o[3][1] = fmaf(p3, v0.y, o[3][1]);
                o[3][2] = fmaf(p3, v0.z, o[3][2]); o[3][3] = fmaf(p3, v0.w, o[3][3]);
                o[3][4] = fmaf(p3, v1.x, o[3][4]); o[3][5] = fmaf(p3, v1.y, o[3][5]);
                o[3][6] = fmaf(p3, v1.z, o[3][6]); o[3][7] = fmaf(p3, v1.w, o[3][7]);
            }
        }
    }

    #pragma unroll
    for (int i = 0; i < 4; i++) {
        int q = tq * 4 + i;
        float inv = 1.f / sm.l[q];
        float* orow = O + ((size_t)(b * NSEQ + q0 + q) * NH + h) * HD;
        float4 w0 = make_float4(o[i][0] * inv, o[i][1] * inv, o[i][2] * inv, o[i][3] * inv);
        float4 w1 = make_float4(o[i][4] * inv, o[i][5] * inv, o[i][6] * inv, o[i][7] * inv);
        *(float4*)(orow + tk * 4)      = w0;
        *(float4*)(orow + 64 + tk * 4) = w1;
    }
}

// ---------------- launch ----------------
extern "C" void kernel_launch(void* const* d_in, const int* in_sizes, int n_in,
                              void* d_out, int out_size)
{
    const float* x  = (const float*)d_in[0];
    const float* Wq = (const float*)d_in[1];
    const float* Wk = (const float*)d_in[2];
    const float* Wv = (const float*)d_in[3];
    const float* Wo = (const float*)d_in[4];
    const float* bo = (const float*)d_in[5];
    float* out = (float*)d_out;

    float *pq, *pk, *pv, *pctx;
    cudaGetSymbolAddress((void**)&pq,   g_q);
    cudaGetSymbolAddress((void**)&pk,   g_k);
    cudaGetSymbolAddress((void**)&pv,   g_v);
    cudaGetSymbolAddress((void**)&pctx, g_ctx);

    __nv_bfloat16 *xh, *xl, *ch_, *cl_, *wqh, *wql, *wkh, *wkl, *wvh, *wvl, *woh, *wol;
    cudaGetSymbolAddress((void**)&xh,  g_xh);
    cudaGetSymbolAddress((void**)&xl,  g_xl);
    cudaGetSymbolAddress((void**)&ch_, g_ctxh);
    cudaGetSymbolAddress((void**)&cl_, g_ctxl);
    cudaGetSymbolAddress((void**)&wqh, g_wqth);
    cudaGetSymbolAddress((void**)&wql, g_wqtl);
    cudaGetSymbolAddress((void**)&wkh, g_wkth);
    cudaGetSymbolAddress((void**)&wkl, g_wktl);
    cudaGetSymbolAddress((void**)&wvh, g_wvth);
    cudaGetSymbolAddress((void**)&wvl, g_wvtl);
    cudaGetSymbolAddress((void**)&woh, g_woth);
    cudaGetSymbolAddress((void**)&wol, g_wotl);

    static bool attrs_set = false;
    if (!attrs_set) {
        cudaFuncSetAttribute(attn2_kernel, cudaFuncAttributeMaxDynamicSharedMemorySize,
                             (int)sizeof(AttnSmem));
        cudaFuncSetAttribute(mma_gemm_kernel, cudaFuncAttributeMaxDynamicSharedMemorySize,
                             GEMM_SMEM);
        attrs_set = true;
    }

    dim3 blk(256);

    // conversions
    split_fp32_kernel<<<(MROWS * DIN / 4 + 255) / 256, blk>>>(x, xh, xl, MROWS * DIN / 4);
    transpose_split_kernel<<<dim3(DOUT / 32, DIN / 32), blk>>>(Wq, wqh, wql, DIN, DOUT);
    transpose_split_kernel<<<dim3(KVDIM / 32, DIN / 32), blk>>>(Wk, wkh, wkl, DIN, KVDIM);
    transpose_split_kernel<<<dim3(KVDIM / 32, DIN / 32), blk>>>(Wv, wvh, wvl, DIN, KVDIM);
    transpose_split_kernel<<<dim3(DOUT / 32, DOUT / 32), blk>>>(Wo, woh, wol, DOUT, DOUT);

    // projections via HMMA split-bf16 GEMM
    mma_gemm_kernel<<<dim3(DOUT / 128, MROWS / 128), blk, GEMM_SMEM>>>(
        xh, xl, wqh, wql, pq, nullptr, DOUT, DIN);
    mma_gemm_kernel<<<dim3(KVDIM / 128, MROWS / 128), blk, GEMM_SMEM>>>(
        xh, xl, wkh, wkl, pk, nullptr, KVDIM, DIN);
    mma_gemm_kernel<<<dim3(KVDIM / 128, MROWS / 128), blk, GEMM_SMEM>>>(
        xh, xl, wvh, wvl, pv, nullptr, KVDIM, DIN);

    // attention
    attn2_kernel<<<dim3(NSEQ / BQ, NH, BSZ), blk, (int)sizeof(AttnSmem)>>>(pq, pk, pv, pctx);

    // output projection
    split_fp32_kernel<<<(MROWS * DOUT / 4 + 255) / 256, blk>>>(pctx, ch_, cl_, MROWS * DOUT / 4);
    mma_gemm_kernel<<<dim3(DOUT / 128, MROWS / 128), blk, GEMM_SMEM>>>(
        ch_, cl_, woh, wol, out, bo, DOUT, DOUT);
}

// round 5
// speedup vs baseline: 4.8977x; 1.6374x over previous
#include <cuda_runtime.h>
#include <cuda_fp16.h>
#include <cstdint>
#include <cstddef>

// Problem constants
#define BSZ   2
#define NSEQ  2048
#define DIN   2048
#define DOUT  2048
#define NH    16
#define NG    4
#define HD    128
#define MROWS (BSZ * NSEQ)   // 4096
#define KVDIM (NG * HD)      // 512

// ---------------- scratch (no allocations allowed) ----------------
__device__ __align__(16) __half g_qh[MROWS * DOUT];
__device__ __align__(16) __half g_ql[MROWS * DOUT];
__device__ __align__(16) __half g_kh[MROWS * KVDIM];
__device__ __align__(16) __half g_kl[MROWS * KVDIM];
__device__ __align__(16) __half g_vh[MROWS * KVDIM];
__device__ __align__(16) __half g_vl[MROWS * KVDIM];
__device__ __align__(16) __half g_xh[MROWS * DIN];
__device__ __align__(16) __half g_xl[MROWS * DIN];
__device__ __align__(16) __half g_ctxh[MROWS * DOUT];
__device__ __align__(16) __half g_ctxl[MROWS * DOUT];
__device__ __align__(16) __half g_wqth[DOUT * DIN];   // Wq^T [N,K]
__device__ __align__(16) __half g_wqtl[DOUT * DIN];
__device__ __align__(16) __half g_wkth[KVDIM * DIN];
__device__ __align__(16) __half g_wktl[KVDIM * DIN];
__device__ __align__(16) __half g_wvth[KVDIM * DIN];
__device__ __align__(16) __half g_wvtl[KVDIM * DIN];
__device__ __align__(16) __half g_woth[DOUT * DOUT];
__device__ __align__(16) __half g_wotl[DOUT * DOUT];

// ---------------- helpers ----------------
__device__ __forceinline__ uint32_t smem_u32(const void* p) {
    uint32_t a;
    asm("{ .reg .u64 t; cvta.to.shared.u64 t, %1; cvt.u32.u64 %0, t; }" : "=r"(a) : "l"(p));
    return a;
}
__device__ __forceinline__ void cp_async16(uint32_t saddr, const void* gaddr) {
    asm volatile("cp.async.cg.shared.global [%0], [%1], 16;" :: "r"(saddr), "l"(gaddr));
}
#define CP_COMMIT() asm volatile("cp.async.commit_group;" ::: "memory")
#define CP_WAIT(n)  asm volatile("cp.async.wait_group %0;" :: "n"(n) : "memory")

__device__ __forceinline__ void ldm_x4(uint32_t& r0, uint32_t& r1, uint32_t& r2, uint32_t& r3,
                                       uint32_t addr) {
    asm volatile("ldmatrix.sync.aligned.m8n8.x4.shared.b16 {%0, %1, %2, %3}, [%4];"
                 : "=r"(r0), "=r"(r1), "=r"(r2), "=r"(r3) : "r"(addr));
}
__device__ __forceinline__ void ldm_x4t(uint32_t& r0, uint32_t& r1, uint32_t& r2, uint32_t& r3,
                                        uint32_t addr) {
    asm volatile("ldmatrix.sync.aligned.m8n8.x4.trans.shared.b16 {%0, %1, %2, %3}, [%4];"
                 : "=r"(r0), "=r"(r1), "=r"(r2), "=r"(r3) : "r"(addr));
}
__device__ __forceinline__ void mma_f16(float* d, const uint32_t* a, const uint32_t* b) {
    asm volatile(
        "mma.sync.aligned.m16n8k16.row.col.f32.f16.f16.f32 "
        "{%0, %1, %2, %3}, {%4, %5, %6, %7}, {%8, %9}, {%0, %1, %2, %3};"
        : "+f"(d[0]), "+f"(d[1]), "+f"(d[2]), "+f"(d[3])
        : "r"(a[0]), "r"(a[1]), "r"(a[2]), "r"(a[3]), "r"(b[0]), "r"(b[1]));
}
__device__ __forceinline__ uint32_t pack_half2(float a, float b) {
    __half2 h = __halves2half2(__float2half_rn(a), __float2half_rn(b));
    return *reinterpret_cast<uint32_t*>(&h);
}
__device__ __forceinline__ void split_store(float v0, float v1, __half* hi, __half* lo) {
    __half h0 = __float2half_rn(v0);
    __half h1 = __float2half_rn(v1);
    __half l0 = __float2half_rn(v0 - __half2float(h0));
    __half l1 = __float2half_rn(v1 - __half2float(h1));
    *reinterpret_cast<__half2*>(hi) = __halves2half2(h0, h1);
    *reinterpret_cast<__half2*>(lo) = __halves2half2(l0, l1);
}

// ---------------- split / transpose conversion kernels ----------------
__global__ __launch_bounds__(256) void split_fp32_kernel(
    const float* __restrict__ in, __half* __restrict__ hi,
    __half* __restrict__ lo, int n4)
{
    int i = blockIdx.x * 256 + threadIdx.x;
    if (i >= n4) return;
    float4 v = ((const float4*)in)[i];
    split_store(v.x, v.y, hi + 4 * (size_t)i,     lo + 4 * (size_t)i);
    split_store(v.z, v.w, hi + 4 * (size_t)i + 2, lo + 4 * (size_t)i + 2);
}

// W[K,N] fp32 -> T[N,K] fp16 hi/lo
__global__ __launch_bounds__(256) void transpose_split_kernel(
    const float* __restrict__ W, __half* __restrict__ Th,
    __half* __restrict__ Tl, int K, int N)
{
    __shared__ float tile[32][33];
    int k0 = blockIdx.y * 32, n0 = blockIdx.x * 32;
    int tx = threadIdx.x & 31, ty = threadIdx.x >> 5;
    #pragma unroll
    for (int r = ty; r < 32; r += 8)
        tile[r][tx] = W[(size_t)(k0 + r) * N + n0 + tx];
    __syncthreads();
    #pragma unroll
    for (int r = ty; r < 32; r += 8) {
        float v = tile[tx][r];
        __half h = __float2half_rn(v);
        __half l = __float2half_rn(v - __half2float(h));
        size_t o = (size_t)(n0 + r) * K + k0 + tx;
        Th[o] = h;
        Tl[o] = l;
    }
}

// ---------------- HMMA split-fp16 GEMM: C = A[M,K] @ BT[N,K]^T ----------------
#define GBK       32
#define LDROW     40
#define TILE_B    (128 * LDROW * 2)
#define STAGE_B   (4 * TILE_B)
#define GEMM_SMEM (2 * STAGE_B)

__global__ __launch_bounds__(256, 1) void mma_gemm_kernel(
    const __half* __restrict__ Ah, const __half* __restrict__ Al,
    const __half* __restrict__ Bh, const __half* __restrict__ Bl,
    float* __restrict__ C, __half* __restrict__ Chf, __half* __restrict__ Clf,
    const float* __restrict__ bias, int N, int K)
{
    extern __shared__ char smem[];
    const uint32_t sb = smem_u32(smem);
    const int tid  = threadIdx.x;
    const int wid  = tid >> 5;
    const int lane = tid & 31;
    const int row0 = blockIdx.y * 128;
    const int col0 = blockIdx.x * 128;
    const int wm   = (wid & 1) * 64;
    const int wn   = (wid >> 1) * 32;

    const __half* gsrc[4] = {Ah, Al, Bh, Bl};

    float acc[4][4][4];
    #pragma unroll
    for (int i = 0; i < 4; i++)
        #pragma unroll
        for (int j = 0; j < 4; j++)
            #pragma unroll
            for (int r = 0; r < 4; r++) acc[i][j][r] = 0.f;

    const int nch = K / GBK;

    auto load_stage = [&](int ch, int stage) {
        const int k0 = ch * GBK;
        const uint32_t sbase = sb + stage * STAGE_B;
        #pragma unroll
        for (int t = 0; t < 8; t++) {
            int idx = tid + t * 256;
            int tensor = idx >> 9;
            int rem = idx & 511;
            int r = rem >> 2;
            int c = rem & 3;
            int grow = (tensor < 2) ? (row0 + r) : (col0 + r);
            const __half* gp = gsrc[tensor] + (size_t)grow * K + k0 + c * 8;
            uint32_t sa = sbase + tensor * TILE_B + (r * LDROW + c * 8) * 2;
            cp_async16(sa, gp);
        }
    };

    load_stage(0, 0);
    CP_COMMIT();

    for (int ch = 0; ch < nch; ch++) {
        if (ch + 1 < nch) {
            load_stage(ch + 1, (ch + 1) & 1);
            CP_COMMIT();
            CP_WAIT(1);
        } else {
            CP_WAIT(0);
        }
        __syncthreads();

        const uint32_t sbase = sb + (ch & 1) * STAGE_B;
        const uint32_t a_hi = sbase + 0 * TILE_B;
        const uint32_t a_lo = sbase + 1 * TILE_B;
        const uint32_t b_hi = sbase + 2 * TILE_B;
        const uint32_t b_lo = sbase + 3 * TILE_B;

        #pragma unroll
        for (int ks = 0; ks < 2; ks++) {
            const uint32_t kb = ks * 32;
            uint32_t fah[4][4], fal[4][4];
            #pragma unroll
            for (int mi = 0; mi < 4; mi++) {
                uint32_t roff = (uint32_t)(wm + mi * 16 + (lane & 15)) * (LDROW * 2)
                              + kb + (lane >> 4) * 16;
                ldm_x4(fah[mi][0], fah[mi][1], fah[mi][2], fah[mi][3], a_hi + roff);
                ldm_x4(fal[mi][0], fal[mi][1], fal[mi][2], fal[mi][3], a_lo + roff);
            }
            uint32_t fbh[4][2], fbl[4][2];
            #pragma unroll
            for (int p = 0; p < 2; p++) {
                uint32_t roff = (uint32_t)(wn + p * 16 + (lane >> 4) * 8 + (lane & 7)) * (LDROW * 2)
                              + kb + ((lane >> 3) & 1) * 16;
                uint32_t r0, r1, r2, r3;
                ldm_x4(r0, r1, r2, r3, b_hi + roff);
                fbh[2 * p][0] = r0; fbh[2 * p][1] = r1;
                fbh[2 * p + 1][0] = r2; fbh[2 * p + 1][1] = r3;
                ldm_x4(r0, r1, r2, r3, b_lo + roff);
                fbl[2 * p][0] = r0; fbl[2 * p][1] = r1;
                fbl[2 * p + 1][0] = r2; fbl[2 * p + 1][1] = r3;
            }
            #pragma unroll
            for (int mi = 0; mi < 4; mi++)
                #pragma unroll
                for (int ni = 0; ni < 4; ni++) {
                    mma_f16(acc[mi][ni], fah[mi], fbh[ni]);
                    mma_f16(acc[mi][ni], fah[mi], fbl[ni]);
                    mma_f16(acc[mi][ni], fal[mi], fbh[ni]);
                }
        }
        __syncthreads();
    }

    const int qrow = lane >> 2;
    const int qcol = (lane & 3) * 2;
    #pragma unroll
    for (int mi = 0; mi < 4; mi++) {
        #pragma unroll
        for (int ni = 0; ni < 4; ni++) {
            int r = row0 + wm + mi * 16 + qrow;
            int c = col0 + wn + ni * 8 + qcol;
            if (Chf != nullptr) {
                split_store(acc[mi][ni][0], acc[mi][ni][1],
                            Chf + (size_t)r * N + c, Clf + (size_t)r * N + c);
                split_store(acc[mi][ni][2], acc[mi][ni][3],
                            Chf + (size_t)(r + 8) * N + c, Clf + (size_t)(r + 8) * N + c);
            } else {
                float b0 = 0.f, b1 = 0.f;
                if (bias != nullptr) { b0 = bias[c]; b1 = bias[c + 1]; }
                float2 v0 = make_float2(acc[mi][ni][0] + b0, acc[mi][ni][1] + b1);
                float2 v1 = make_float2(acc[mi][ni][2] + b0, acc[mi][ni][3] + b1);
                *(float2*)(C + (size_t)r * N + c)       = v0;
                *(float2*)(C + (size_t)(r + 8) * N + c) = v1;
            }
        }
    }
}

// ---------------- HMMA split-fp16 causal GQA flash attention ----------------
// CTA: (b,h) x 64 query rows; 4 warps x 16 rows; key blocks of 64.
#define AROWB 136                         // halfs per padded row (272 B)
#define ATILE (64 * AROWB * 2)            // 17408 B
#define ATTN_SMEM (6 * ATILE)             // 104448 B

__global__ __launch_bounds__(128, 1) void attn3_kernel(
    const __half* __restrict__ Qh, const __half* __restrict__ Ql,
    const __half* __restrict__ Kh, const __half* __restrict__ Kl,
    const __half* __restrict__ Vh, const __half* __restrict__ Vl,
    __half* __restrict__ Ch, __half* __restrict__ Cl)
{
    extern __shared__ char smem[];
    const uint32_t sb = smem_u32(smem);
    const int tid  = threadIdx.x;
    const int wid  = tid >> 5;
    const int lane = tid & 31;
    const int b = blockIdx.z;
    const int h = blockIdx.y;
    const int g = h >> 2;
    const int qb = gridDim.x - 1 - blockIdx.x;
    const int q0 = qb * 64;
    const int wrow = wid * 16;

    const uint32_t s_qh = sb + 0 * ATILE, s_ql = sb + 1 * ATILE;
    const uint32_t s_kh = sb + 2 * ATILE, s_kl = sb + 3 * ATILE;
    const uint32_t s_vh = sb + 4 * ATILE, s_vl = sb + 5 * ATILE;

    const float scale = 0.08838834764831845f;

    // load Q tile (64 x 128 halfs, hi+lo)
    #pragma unroll
    for (int t = 0; t < 8; t++) {
        int idx = tid + t * 128;
        int r = idx >> 4;
        int c = idx & 15;
        size_t go = ((size_t)(b * NSEQ + q0 + r) * NH + h) * HD + c * 8;
        uint32_t so = (uint32_t)r * (AROWB * 2) + c * 16;
        cp_async16(s_qh + so, Qh + go);
        cp_async16(s_ql + so, Ql + go);
    }
    CP_COMMIT();

    float m0 = -1e30f, m1 = -1e30f, l0 = 0.f, l1 = 0.f;
    float o[16][4];
    #pragma unroll
    for (int n = 0; n < 16; n++)
        #pragma unroll
        for (int r = 0; r < 4; r++) o[n][r] = 0.f;

    for (int kb = 0; kb <= qb; kb++) {
        __syncthreads();   // previous block's smem reads done
        #pragma unroll
        for (int t = 0; t < 8; t++) {
            int idx = tid + t * 128;
            int r = idx >> 4;
            int c = idx & 15;
            size_t go = ((size_t)(b * NSEQ + kb * 64 + r) * NG + g) * HD + c * 8;
            uint32_t so = (uint32_t)r * (AROWB * 2) + c * 16;
            cp_async16(s_kh + so, Kh + go);
            cp_async16(s_kl + so, Kl + go);
            cp_async16(s_vh + so, Vh + go);
            cp_async16(s_vl + so, Vl + go);
        }
        CP_COMMIT();
        CP_WAIT(0);
        __syncthreads();

        // ---- scores: S[16 x 64] = Q_tile @ K_block^T (3-pass split) ----
        float sacc[8][4];
        #pragma unroll
        for (int j = 0; j < 8; j++)
            #pragma unroll
            for (int r = 0; r < 4; r++) sacc[j][r] = 0.f;

        #pragma unroll
        for (int kc = 0; kc < 8; kc++) {
            uint32_t aoff = (uint32_t)(wrow + (lane & 15)) * (AROWB * 2)
                          + kc * 32 + (lane >> 4) * 16;
            uint32_t fah[4], fal[4];
            ldm_x4(fah[0], fah[1], fah[2], fah[3], s_qh + aoff);
            ldm_x4(fal[0], fal[1], fal[2], fal[3], s_ql + aoff);
            uint32_t fbh[8][2], fbl[8][2];
            #pragma unroll
            for (int p = 0; p < 4; p++) {
                uint32_t boff = (uint32_t)(p * 16 + (lane >> 4) * 8 + (lane & 7)) * (AROWB * 2)
                              + kc * 32 + ((lane >> 3) & 1) * 16;
                uint32_t r0, r1, r2, r3;
                ldm_x4(r0, r1, r2, r3, s_kh + boff);
                fbh[2 * p][0] = r0; fbh[2 * p][1] = r1;
                fbh[2 * p + 1][0] = r2; fbh[2 * p + 1][1] = r3;
                ldm_x4(r0, r1, r2, r3, s_kl + boff);
                fbl[2 * p][0] = r0; fbl[2 * p][1] = r1;
                fbl[2 * p + 1][0] = r2; fbl[2 * p + 1][1] = r3;
            }
            #pragma unroll
            for (int j = 0; j < 8; j++) {
                mma_f16(sacc[j], fah, fbh[j]);
                mma_f16(sacc[j], fah, fbl[j]);
                mma_f16(sacc[j], fal, fbh[j]);
            }
        }

        // ---- scale + causal mask + row stats ----
        const bool diag = (kb == qb);
        const int qr0 = q0 + wrow + (lane >> 2);
        float mb0 = -1e30f, mb1 = -1e30f;
        #pragma unroll
        for (int j = 0; j < 8; j++) {
            #pragma unroll
            for (int r = 0; r < 4; r++) sacc[j][r] *= scale;
            if (diag) {
                int key = kb * 64 + j * 8 + (lane & 3) * 2;
                if (key     > qr0)     sacc[j][0] = -1e30f;
                if (key + 1 > qr0)     sacc[j][1] = -1e30f;
                if (key     > qr0 + 8) sacc[j][2] = -1e30f;
                if (key + 1 > qr0 + 8) sacc[j][3] = -1e30f;
            }
            mb0 = fmaxf(mb0, fmaxf(sacc[j][0], sacc[j][1]));
            mb1 = fmaxf(mb1, fmaxf(sacc[j][2], sacc[j][3]));
        }
        mb0 = fmaxf(mb0, __shfl_xor_sync(0xFFFFFFFFu, mb0, 1));
        mb0 = fmaxf(mb0, __shfl_xor_sync(0xFFFFFFFFu, mb0, 2));
        mb1 = fmaxf(mb1, __shfl_xor_sync(0xFFFFFFFFu, mb1, 1));
        mb1 = fmaxf(mb1, __shfl_xor_sync(0xFFFFFFFFu, mb1, 2));

        float mn0 = fmaxf(m0, mb0), mn1 = fmaxf(m1, mb1);
        float a0 = __expf(m0 - mn0), a1 = __expf(m1 - mn1);
        m0 = mn0; m1 = mn1;

        // ---- exp + split P into fp16 hi/lo A-fragments ----
        float s0 = 0.f, s1 = 0.f;
        uint32_t pha[4][4], pla[4][4];
        #pragma unroll
        for (int j = 0; j < 8; j++) {
            float p0 = __expf(sacc[j][0] - mn0);
            float p1 = __expf(sacc[j][1] - mn0);
            float p2 = __expf(sacc[j][2] - mn1);
            float p3 = __expf(sacc[j][3] - mn1);
            s0 += p0 + p1;
            s1 += p2 + p3;
            __half h0 = __float2half_rn(p0), h1 = __float2half_rn(p1);
            __half h2 = __float2half_rn(p2), h3 = __float2half_rn(p3);
            float q0f = p0 - __half2float(h0), q1f = p1 - __half2float(h1);
            float q2f = p2 - __half2float(h2), q3f = p3 - __half2float(h3);
            int t = j >> 1, w = (j & 1) * 2;
            __half2 hh01 = __halves2half2(h0, h1);
            __half2 hh23 = __halves2half2(h2, h3);
            pha[t][0 + w] = *reinterpret_cast<uint32_t*>(&hh01);
            pha[t][1 + w] = *reinterpret_cast<uint32_t*>(&hh23);
            pla[t][0 + w] = pack_half2(q0f, q1f);
            pla[t][1 + w] = pack_half2(q2f, q3f);
        }
        s0 += __shfl_xor_sync(0xFFFFFFFFu, s0, 1);
        s0 += __shfl_xor_sync(0xFFFFFFFFu, s0, 2);
        s1 += __shfl_xor_sync(0xFFFFFFFFu, s1, 1);
        s1 += __shfl_xor_sync(0xFFFFFFFFu, s1, 2);
        l0 = l0 * a0 + s0;
        l1 = l1 * a1 + s1;

        // rescale O
        #pragma unroll
        for (int n = 0; n < 16; n++) {
            o[n][0] *= a0; o[n][1] *= a0;
            o[n][2] *= a1; o[n][3] *= a1;
        }

        // ---- PV: O[16 x 128] += P @ V (3-pass split, V via ldmatrix.trans) ----
        #pragma unroll
        for (int np = 0; np < 8; np++) {
            #pragma unroll
            for (int t = 0; t < 4; t++) {
                uint32_t vaddr = (uint32_t)(16 * t + (lane & 7) + ((lane >> 3) & 1) * 8) * (AROWB * 2)
                               + (np * 16 + (lane >> 4) * 8) * 2;
                uint32_t h0, h1, h2, h3, e0, e1, e2, e3;
                ldm_x4t(h0, h1, h2, h3, s_vh + vaddr);
                ldm_x4t(e0, e1, e2, e3, s_vl + vaddr);
                uint32_t bh0[2] = {h0, h1}, bh1[2] = {h2, h3};
                uint32_t bl0[2] = {e0, e1}, bl1[2] = {e2, e3};
                mma_f16(o[2 * np],     pha[t], bh0);
                mma_f16(o[2 * np],     pha[t], bl0);
                mma_f16(o[2 * np],     pla[t], bh0);
                mma_f16(o[2 * np + 1], pha[t], bh1);
                mma_f16(o[2 * np + 1], pha[t], bl1);
                mma_f16(o[2 * np + 1], pla[t], bh1);
            }
        }
    }

    // ---- epilogue: normalize, split to fp16 hi/lo, store ctx ----
    const float inv0 = 1.f / l0, inv1 = 1.f / l1;
    const int r0g = q0 + wrow + (lane >> 2);
    const int r1g = r0g + 8;
    #pragma unroll
    for (int n = 0; n < 16; n++) {
        int d = n * 8 + (lane & 3) * 2;
        size_t off0 = ((size_t)(b * NSEQ + r0g) * NH + h) * HD + d;
        size_t off1 = ((size_t)(b * NSEQ + r1g) * NH + h) * HD + d;
        split_store(o[n][0] * inv0, o[n][1] * inv0, Ch + off0, Cl + off0);
        split_store(o[n][2] * inv1, o[n][3] * inv1, Ch + off1, Cl + off1);
    }
}

// ---------------- launch ----------------
extern "C" void kernel_launch(void* const* d_in, const int* in_sizes, int n_in,
                              void* d_out, int out_size)
{
    const float* x  = (const float*)d_in[0];
    const float* Wq = (const float*)d_in[1];
    const float* Wk = (const float*)d_in[2];
    const float* Wv = (const float*)d_in[3];
    const float* Wo = (const float*)d_in[4];
    const float* bo = (const float*)d_in[5];
    float* out = (float*)d_out;

    __half *qh, *ql, *kh, *kl, *vh, *vl, *xh, *xl, *ch_, *cl_;
    __half *wqh, *wql, *wkh, *wkl, *wvh, *wvl, *woh, *wol;
    cudaGetSymbolAddress((void**)&qh,  g_qh);
    cudaGetSymbolAddress((void**)&ql,  g_ql);
    cudaGetSymbolAddress((void**)&kh,  g_kh);
    cudaGetSymbolAddress((void**)&kl,  g_kl);
    cudaGetSymbolAddress((void**)&vh,  g_vh);
    cudaGetSymbolAddress((void**)&vl,  g_vl);
    cudaGetSymbolAddress((void**)&xh,  g_xh);
    cudaGetSymbolAddress((void**)&xl,  g_xl);
    cudaGetSymbolAddress((void**)&ch_, g_ctxh);
    cudaGetSymbolAddress((void**)&cl_, g_ctxl);
    cudaGetSymbolAddress((void**)&wqh, g_wqth);
    cudaGetSymbolAddress((void**)&wql, g_wqtl);
    cudaGetSymbolAddress((void**)&wkh, g_wkth);
    cudaGetSymbolAddress((void**)&wkl, g_wktl);
    cudaGetSymbolAddress((void**)&wvh, g_wvth);
    cudaGetSymbolAddress((void**)&wvl, g_wvtl);
    cudaGetSymbolAddress((void**)&woh, g_woth);
    cudaGetSymbolAddress((void**)&wol, g_wotl);

    static bool attrs_set = false;
    if (!attrs_set) {
        cudaFuncSetAttribute(mma_gemm_kernel, cudaFuncAttributeMaxDynamicSharedMemorySize,
                             GEMM_SMEM);
        cudaFuncSetAttribute(attn3_kernel, cudaFuncAttributeMaxDynamicSharedMemorySize,
                             ATTN_SMEM);
        attrs_set = true;
    }

    dim3 blk(256);

    // conversions
    split_fp32_kernel<<<(MROWS * DIN / 4 + 255) / 256, blk>>>(x, xh, xl, MROWS * DIN / 4);
    transpose_split_kernel<<<dim3(DOUT / 32, DIN / 32), blk>>>(Wq, wqh, wql, DIN, DOUT);
    transpose_split_kernel<<<dim3(KVDIM / 32, DIN / 32), blk>>>(Wk, wkh, wkl, DIN, KVDIM);
    transpose_split_kernel<<<dim3(KVDIM / 32, DIN / 32), blk>>>(Wv, wvh, wvl, DIN, KVDIM);
    transpose_split_kernel<<<dim3(DOUT / 32, DOUT / 32), blk>>>(Wo, woh, wol, DOUT, DOUT);

    // projections (fp16 hi/lo outputs)
    mma_gemm_kernel<<<dim3(DOUT / 128, MROWS / 128), blk, GEMM_SMEM>>>(
        xh, xl, wqh, wql, nullptr, qh, ql, nullptr, DOUT, DIN);
    mma_gemm_kernel<<<dim3(KVDIM / 128, MROWS / 128), blk, GEMM_SMEM>>>(
        xh, xl, wkh, wkl, nullptr, kh, kl, nullptr, KVDIM, DIN);
    mma_gemm_kernel<<<dim3(KVDIM / 128, MROWS / 128), blk, GEMM_SMEM>>>(
        xh, xl, wvh, wvl, nullptr, vh, vl, nullptr, KVDIM, DIN);

    // attention (fp16 hi/lo ctx output)
    attn3_kernel<<<dim3(NSEQ / 64, NH, BSZ), dim3(128), ATTN_SMEM>>>(
        qh, ql, kh, kl, vh, vl, ch_, cl_);

    // output projection (fp32 + bias)
    mma_gemm_kernel<<<dim3(DOUT / 128, MROWS / 128), blk, GEMM_SMEM>>>(
        ch_, cl_, woh, wol, out, nullptr, nullptr, bo, DOUT, DOUT);
}

// round 6
// speedup vs baseline: 7.1830x; 1.4666x over previous
#include <cuda_runtime.h>
#include <cuda_fp16.h>
#include <cstdint>
#include <cstddef>

// Problem constants
#define BSZ   2
#define NSEQ  2048
#define DIN   2048
#define DOUT  2048
#define NH    16
#define NG    4
#define HD    128
#define MROWS (BSZ * NSEQ)   // 4096
#define KVDIM (NG * HD)      // 512

// ---------------- scratch (no allocations allowed) ----------------
__device__ __align__(16) __half g_qh[MROWS * DOUT];     // q single fp16
__device__ __align__(16) __half g_kh[MROWS * KVDIM];    // k hi
__device__ __align__(16) __half g_kl[MROWS * KVDIM];    // k lo
__device__ __align__(16) __half g_vh[MROWS * KVDIM];
__device__ __align__(16) __half g_vl[MROWS * KVDIM];
__device__ __align__(16) __half g_x16[MROWS * DIN];     // x single fp16
__device__ __align__(16) __half g_ctx16[MROWS * DOUT];  // ctx single fp16
__device__ __align__(16) __half g_wqth[DOUT * DIN];     // W^T [N,K] hi/lo
__device__ __align__(16) __half g_wqtl[DOUT * DIN];
__device__ __align__(16) __half g_wkth[KVDIM * DIN];
__device__ __align__(16) __half g_wktl[KVDIM * DIN];
__device__ __align__(16) __half g_wvth[KVDIM * DIN];
__device__ __align__(16) __half g_wvtl[KVDIM * DIN];
__device__ __align__(16) __half g_woth[DOUT * DOUT];
__device__ __align__(16) __half g_wotl[DOUT * DOUT];

// ---------------- helpers ----------------
__device__ __forceinline__ uint32_t smem_u32(const void* p) {
    uint32_t a;
    asm("{ .reg .u64 t; cvta.to.shared.u64 t, %1; cvt.u32.u64 %0, t; }" : "=r"(a) : "l"(p));
    return a;
}
__device__ __forceinline__ void cp_async16(uint32_t saddr, const void* gaddr) {
    asm volatile("cp.async.cg.shared.global [%0], [%1], 16;" :: "r"(saddr), "l"(gaddr));
}
#define CP_COMMIT() asm volatile("cp.async.commit_group;" ::: "memory")
#define CP_WAIT(n)  asm volatile("cp.async.wait_group %0;" :: "n"(n) : "memory")

__device__ __forceinline__ void ldm_x4(uint32_t& r0, uint32_t& r1, uint32_t& r2, uint32_t& r3,
                                       uint32_t addr) {
    asm volatile("ldmatrix.sync.aligned.m8n8.x4.shared.b16 {%0, %1, %2, %3}, [%4];"
                 : "=r"(r0), "=r"(r1), "=r"(r2), "=r"(r3) : "r"(addr));
}
__device__ __forceinline__ void ldm_x4t(uint32_t& r0, uint32_t& r1, uint32_t& r2, uint32_t& r3,
                                        uint32_t addr) {
    asm volatile("ldmatrix.sync.aligned.m8n8.x4.trans.shared.b16 {%0, %1, %2, %3}, [%4];"
                 : "=r"(r0), "=r"(r1), "=r"(r2), "=r"(r3) : "r"(addr));
}
__device__ __forceinline__ void mma_f16(float* d, const uint32_t* a, const uint32_t* b) {
    asm volatile(
        "mma.sync.aligned.m16n8k16.row.col.f32.f16.f16.f32 "
        "{%0, %1, %2, %3}, {%4, %5, %6, %7}, {%8, %9}, {%0, %1, %2, %3};"
        : "+f"(d[0]), "+f"(d[1]), "+f"(d[2]), "+f"(d[3])
        : "r"(a[0]), "r"(a[1]), "r"(a[2]), "r"(a[3]), "r"(b[0]), "r"(b[1]));
}
__device__ __forceinline__ uint32_t pack_half2(float a, float b) {
    __half2 h = __halves2half2(__float2half_rn(a), __float2half_rn(b));
    return *reinterpret_cast<uint32_t*>(&h);
}
__device__ __forceinline__ void split_store(float v0, float v1, __half* hi, __half* lo) {
    __half h0 = __float2half_rn(v0);
    __half h1 = __float2half_rn(v1);
    __half l0 = __float2half_rn(v0 - __half2float(h0));
    __half l1 = __float2half_rn(v1 - __half2float(h1));
    *reinterpret_cast<__half2*>(hi) = __halves2half2(h0, h1);
    *reinterpret_cast<__half2*>(lo) = __halves2half2(l0, l1);
}

// ---------------- conversion kernels ----------------
__global__ __launch_bounds__(256) void round_fp16_kernel(
    const float* __restrict__ in, __half* __restrict__ out, int n4)
{
    int i = blockIdx.x * 256 + threadIdx.x;
    if (i >= n4) return;
    float4 v = ((const float4*)in)[i];
    __half2 a = __halves2half2(__float2half_rn(v.x), __float2half_rn(v.y));
    __half2 b = __halves2half2(__float2half_rn(v.z), __float2half_rn(v.w));
    ((__half2*)out)[2 * i]     = a;
    ((__half2*)out)[2 * i + 1] = b;
}

// W[K,N] fp32 -> T[N,K] fp16 hi/lo
__global__ __launch_bounds__(256) void transpose_split_kernel(
    const float* __restrict__ W, __half* __restrict__ Th,
    __half* __restrict__ Tl, int K, int N)
{
    __shared__ float tile[32][33];
    int k0 = blockIdx.y * 32, n0 = blockIdx.x * 32;
    int tx = threadIdx.x & 31, ty = threadIdx.x >> 5;
    #pragma unroll
    for (int r = ty; r < 32; r += 8)
        tile[r][tx] = W[(size_t)(k0 + r) * N + n0 + tx];
    __syncthreads();
    #pragma unroll
    for (int r = ty; r < 32; r += 8) {
        float v = tile[tx][r];
        __half h = __float2half_rn(v);
        __half l = __float2half_rn(v - __half2float(h));
        size_t o = (size_t)(n0 + r) * K + k0 + tx;
        Th[o] = h;
        Tl[o] = l;
    }
}

// ---------------- HMMA 2-pass GEMM: C = A[M,K] @ (Bh+Bl)[N,K]^T ----------------
// A plain fp16, B exactly split. CTA 128x128, BK=32, 8 warps (2M x 4N).
#define GBK       32
#define LDROW     40
#define TILE_B    (128 * LDROW * 2)        // 10240 B
#define STAGE_B   (3 * TILE_B)             // 30720 B (A, Bh, Bl)
#define GEMM_SMEM (2 * STAGE_B)            // 61440 B

__global__ __launch_bounds__(256, 2) void mma_gemm_kernel(
    const __half* __restrict__ A,
    const __half* __restrict__ Bh, const __half* __restrict__ Bl,
    float* __restrict__ C, __half* __restrict__ Chf, __half* __restrict__ Clf,
    const float* __restrict__ bias, int N, int K)
{
    extern __shared__ char smem[];
    const uint32_t sb = smem_u32(smem);
    const int tid  = threadIdx.x;
    const int wid  = tid >> 5;
    const int lane = tid & 31;
    const int row0 = blockIdx.y * 128;
    const int col0 = blockIdx.x * 128;
    const int wm   = (wid & 1) * 64;
    const int wn   = (wid >> 1) * 32;

    const __half* gsrc[3] = {A, Bh, Bl};

    float acc[4][4][4];
    #pragma unroll
    for (int i = 0; i < 4; i++)
        #pragma unroll
        for (int j = 0; j < 4; j++)
            #pragma unroll
            for (int r = 0; r < 4; r++) acc[i][j][r] = 0.f;

    const int nch = K / GBK;

    auto load_stage = [&](int ch, int stage) {
        const int k0 = ch * GBK;
        const uint32_t sbase = sb + stage * STAGE_B;
        #pragma unroll
        for (int t = 0; t < 6; t++) {
            int idx = tid + t * 256;            // 0..1535
            int tensor = idx >> 9;              // 0..2
            int rem = idx & 511;
            int r = rem >> 2;                   // 0..127
            int c = rem & 3;
            int grow = (tensor == 0) ? (row0 + r) : (col0 + r);
            const __half* gp = gsrc[tensor] + (size_t)grow * K + k0 + c * 8;
            uint32_t sa = sbase + tensor * TILE_B + (r * LDROW + c * 8) * 2;
            cp_async16(sa, gp);
        }
    };

    load_stage(0, 0);
    CP_COMMIT();

    for (int ch = 0; ch < nch; ch++) {
        if (ch + 1 < nch) {
            load_stage(ch + 1, (ch + 1) & 1);
            CP_COMMIT();
            CP_WAIT(1);
        } else {
            CP_WAIT(0);
        }
        __syncthreads();

        const uint32_t sbase = sb + (ch & 1) * STAGE_B;
        const uint32_t a_t  = sbase + 0 * TILE_B;
        const uint32_t b_hi = sbase + 1 * TILE_B;
        const uint32_t b_lo = sbase + 2 * TILE_B;

        #pragma unroll
        for (int ks = 0; ks < 2; ks++) {
            const uint32_t kb = ks * 32;
            uint32_t fa[4][4];
            #pragma unroll
            for (int mi = 0; mi < 4; mi++) {
                uint32_t roff = (uint32_t)(wm + mi * 16 + (lane & 15)) * (LDROW * 2)
                              + kb + (lane >> 4) * 16;
                ldm_x4(fa[mi][0], fa[mi][1], fa[mi][2], fa[mi][3], a_t + roff);
            }
            uint32_t fbh[4][2], fbl[4][2];
            #pragma unroll
            for (int p = 0; p < 2; p++) {
                uint32_t roff = (uint32_t)(wn + p * 16 + (lane >> 4) * 8 + (lane & 7)) * (LDROW * 2)
                              + kb + ((lane >> 3) & 1) * 16;
                uint32_t r0, r1, r2, r3;
                ldm_x4(r0, r1, r2, r3, b_hi + roff);
                fbh[2 * p][0] = r0; fbh[2 * p][1] = r1;
                fbh[2 * p + 1][0] = r2; fbh[2 * p + 1][1] = r3;
                ldm_x4(r0, r1, r2, r3, b_lo + roff);
                fbl[2 * p][0] = r0; fbl[2 * p][1] = r1;
                fbl[2 * p + 1][0] = r2; fbl[2 * p + 1][1] = r3;
            }
            #pragma unroll
            for (int mi = 0; mi < 4; mi++)
                #pragma unroll
                for (int ni = 0; ni < 4; ni++) {
                    mma_f16(acc[mi][ni], fa[mi], fbh[ni]);
                    mma_f16(acc[mi][ni], fa[mi], fbl[ni]);
                }
        }
        __syncthreads();
    }

    const int qrow = lane >> 2;
    const int qcol = (lane & 3) * 2;
    #pragma unroll
    for (int mi = 0; mi < 4; mi++) {
        #pragma unroll
        for (int ni = 0; ni < 4; ni++) {
            int r = row0 + wm + mi * 16 + qrow;
            int c = col0 + wn + ni * 8 + qcol;
            if (C != nullptr) {
                float b0 = 0.f, b1 = 0.f;
                if (bias != nullptr) { b0 = bias[c]; b1 = bias[c + 1]; }
                float2 v0 = make_float2(acc[mi][ni][0] + b0, acc[mi][ni][1] + b1);
                float2 v1 = make_float2(acc[mi][ni][2] + b0, acc[mi][ni][3] + b1);
                *(float2*)(C + (size_t)r * N + c)       = v0;
                *(float2*)(C + (size_t)(r + 8) * N + c) = v1;
            } else if (Clf != nullptr) {
                split_store(acc[mi][ni][0], acc[mi][ni][1],
                            Chf + (size_t)r * N + c, Clf + (size_t)r * N + c);
                split_store(acc[mi][ni][2], acc[mi][ni][3],
                            Chf + (size_t)(r + 8) * N + c, Clf + (size_t)(r + 8) * N + c);
            } else {
                *(uint32_t*)(Chf + (size_t)r * N + c) =
                    pack_half2(acc[mi][ni][0], acc[mi][ni][1]);
                *(uint32_t*)(Chf + (size_t)(r + 8) * N + c) =
                    pack_half2(acc[mi][ni][2], acc[mi][ni][3]);
            }
        }
    }
}

// ---------------- HMMA 2-pass causal GQA flash attention ----------------
// CTA: (b,h) x 64 query rows; 4 warps x 16 rows; key blocks of 64.
// Q plain fp16; K,V exactly split hi/lo; P plain fp16.
#define AROWB 136                          // halfs per padded row (272 B)
#define ATILE (64 * AROWB * 2)             // 17408 B
#define ATTN_SMEM (5 * ATILE)              // 87040 B

__global__ __launch_bounds__(128, 2) void attn4_kernel(
    const __half* __restrict__ Q,
    const __half* __restrict__ Kh, const __half* __restrict__ Kl,
    const __half* __restrict__ Vh, const __half* __restrict__ Vl,
    __half* __restrict__ Cx)
{
    extern __shared__ char smem[];
    const uint32_t sb = smem_u32(smem);
    const int tid  = threadIdx.x;
    const int wid  = tid >> 5;
    const int lane = tid & 31;
    const int b = blockIdx.z;
    const int h = blockIdx.y;
    const int g = h >> 2;
    const int qb = gridDim.x - 1 - blockIdx.x;
    const int q0 = qb * 64;
    const int wrow = wid * 16;

    const uint32_t s_q  = sb + 0 * ATILE;
    const uint32_t s_kh = sb + 1 * ATILE, s_kl = sb + 2 * ATILE;
    const uint32_t s_vh = sb + 3 * ATILE, s_vl = sb + 4 * ATILE;

    const float scale = 0.08838834764831845f;

    // load Q tile (64 x 128 halfs)
    #pragma unroll
    for (int t = 0; t < 8; t++) {
        int idx = tid + t * 128;
        int r = idx >> 4;
        int c = idx & 15;
        size_t go = ((size_t)(b * NSEQ + q0 + r) * NH + h) * HD + c * 8;
        cp_async16(s_q + (uint32_t)r * (AROWB * 2) + c * 16, Q + go);
    }
    CP_COMMIT();

    float m0 = -1e30f, m1 = -1e30f, l0 = 0.f, l1 = 0.f;
    float o[16][4];
    #pragma unroll
    for (int n = 0; n < 16; n++)
        #pragma unroll
        for (int r = 0; r < 4; r++) o[n][r] = 0.f;

    for (int kb = 0; kb <= qb; kb++) {
        __syncthreads();
        #pragma unroll
        for (int t = 0; t < 8; t++) {
            int idx = tid + t * 128;
            int r = idx >> 4;
            int c = idx & 15;
            size_t go = ((size_t)(b * NSEQ + kb * 64 + r) * NG + g) * HD + c * 8;
            uint32_t so = (uint32_t)r * (AROWB * 2) + c * 16;
            cp_async16(s_kh + so, Kh + go);
            cp_async16(s_kl + so, Kl + go);
            cp_async16(s_vh + so, Vh + go);
            cp_async16(s_vl + so, Vl + go);
        }
        CP_COMMIT();
        CP_WAIT(0);
        __syncthreads();

        // ---- scores: S[16 x 64] = Q @ (Kh+Kl)^T ----
        float sacc[8][4];
        #pragma unroll
        for (int j = 0; j < 8; j++)
            #pragma unroll
            for (int r = 0; r < 4; r++) sacc[j][r] = 0.f;

        #pragma unroll
        for (int kc = 0; kc < 8; kc++) {
            uint32_t aoff = (uint32_t)(wrow + (lane & 15)) * (AROWB * 2)
                          + kc * 32 + (lane >> 4) * 16;
            uint32_t fa[4];
            ldm_x4(fa[0], fa[1], fa[2], fa[3], s_q + aoff);
            uint32_t fbh[8][2], fbl[8][2];
            #pragma unroll
            for (int p = 0; p < 4; p++) {
                uint32_t boff = (uint32_t)(p * 16 + (lane >> 4) * 8 + (lane & 7)) * (AROWB * 2)
                              + kc * 32 + ((lane >> 3) & 1) * 16;
                uint32_t r0, r1, r2, r3;
                ldm_x4(r0, r1, r2, r3, s_kh + boff);
                fbh[2 * p][0] = r0; fbh[2 * p][1] = r1;
                fbh[2 * p + 1][0] = r2; fbh[2 * p + 1][1] = r3;
                ldm_x4(r0, r1, r2, r3, s_kl + boff);
                fbl[2 * p][0] = r0; fbl[2 * p][1] = r1;
                fbl[2 * p + 1][0] = r2; fbl[2 * p + 1][1] = r3;
            }
            #pragma unroll
            for (int j = 0; j < 8; j++) {
                mma_f16(sacc[j], fa, fbh[j]);
                mma_f16(sacc[j], fa, fbl[j]);
            }
        }

        // ---- scale + causal mask + row stats ----
        const bool diag = (kb == qb);
        const int qr0 = q0 + wrow + (lane >> 2);
        float mb0 = -1e30f, mb1 = -1e30f;
        #pragma unroll
        for (int j = 0; j < 8; j++) {
            #pragma unroll
            for (int r = 0; r < 4; r++) sacc[j][r] *= scale;
            if (diag) {
                int key = kb * 64 + j * 8 + (lane & 3) * 2;
                if (key     > qr0)     sacc[j][0] = -1e30f;
                if (key + 1 > qr0)     sacc[j][1] = -1e30f;
                if (key     > qr0 + 8) sacc[j][2] = -1e30f;
                if (key + 1 > qr0 + 8) sacc[j][3] = -1e30f;
            }
            mb0 = fmaxf(mb0, fmaxf(sacc[j][0], sacc[j][1]));
            mb1 = fmaxf(mb1, fmaxf(sacc[j][2], sacc[j][3]));
        }
        mb0 = fmaxf(mb0, __shfl_xor_sync(0xFFFFFFFFu, mb0, 1));
        mb0 = fmaxf(mb0, __shfl_xor_sync(0xFFFFFFFFu, mb0, 2));
        mb1 = fmaxf(mb1, __shfl_xor_sync(0xFFFFFFFFu, mb1, 1));
        mb1 = fmaxf(mb1, __shfl_xor_sync(0xFFFFFFFFu, mb1, 2));

        float mn0 = fmaxf(m0, mb0), mn1 = fmaxf(m1, mb1);
        float a0 = __expf(m0 - mn0), a1 = __expf(m1 - mn1);
        m0 = mn0; m1 = mn1;

        // ---- exp + pack P as plain fp16 A-fragments ----
        float s0 = 0.f, s1 = 0.f;
        uint32_t pa[4][4];
        #pragma unroll
        for (int j = 0; j < 8; j++) {
            float p0 = __expf(sacc[j][0] - mn0);
            float p1 = __expf(sacc[j][1] - mn0);
            float p2 = __expf(sacc[j][2] - mn1);
            float p3 = __expf(sacc[j][3] - mn1);
            s0 += p0 + p1;
            s1 += p2 + p3;
            int t = j >> 1, w = (j & 1) * 2;
            pa[t][0 + w] = pack_half2(p0, p1);
            pa[t][1 + w] = pack_half2(p2, p3);
        }
        s0 += __shfl_xor_sync(0xFFFFFFFFu, s0, 1);
        s0 += __shfl_xor_sync(0xFFFFFFFFu, s0, 2);
        s1 += __shfl_xor_sync(0xFFFFFFFFu, s1, 1);
        s1 += __shfl_xor_sync(0xFFFFFFFFu, s1, 2);
        l0 = l0 * a0 + s0;
        l1 = l1 * a1 + s1;

        #pragma unroll
        for (int n = 0; n < 16; n++) {
            o[n][0] *= a0; o[n][1] *= a0;
            o[n][2] *= a1; o[n][3] *= a1;
        }

        // ---- PV: O[16 x 128] += P @ (Vh+Vl) ----
        #pragma unroll
        for (int np = 0; np < 8; np++) {
            #pragma unroll
            for (int t = 0; t < 4; t++) {
                uint32_t vaddr = (uint32_t)(16 * t + (lane & 7) + ((lane >> 3) & 1) * 8) * (AROWB * 2)
                               + (np * 16 + (lane >> 4) * 8) * 2;
                uint32_t h0, h1, h2, h3, e0, e1, e2, e3;
                ldm_x4t(h0, h1, h2, h3, s_vh + vaddr);
                ldm_x4t(e0, e1, e2, e3, s_vl + vaddr);
                uint32_t bh0[2] = {h0, h1}, bh1[2] = {h2, h3};
                uint32_t bl0[2] = {e0, e1}, bl1[2] = {e2, e3};
                mma_f16(o[2 * np],     pa[t], bh0);
                mma_f16(o[2 * np],     pa[t], bl0);
                mma_f16(o[2 * np + 1], pa[t], bh1);
                mma_f16(o[2 * np + 1], pa[t], bl1);
            }
        }
    }

    // ---- epilogue: normalize, store ctx as plain fp16 ----
    const float inv0 = 1.f / l0, inv1 = 1.f / l1;
    const int r0g = q0 + wrow + (lane >> 2);
    const int r1g = r0g + 8;
    #pragma unroll
    for (int n = 0; n < 16; n++) {
        int d = n * 8 + (lane & 3) * 2;
        size_t off0 = ((size_t)(b * NSEQ + r0g) * NH + h) * HD + d;
        size_t off1 = ((size_t)(b * NSEQ + r1g) * NH + h) * HD + d;
        *(uint32_t*)(Cx + off0) = pack_half2(o[n][0] * inv0, o[n][1] * inv0);
        *(uint32_t*)(Cx + off1) = pack_half2(o[n][2] * inv1, o[n][3] * inv1);
    }
}

// ---------------- launch ----------------
extern "C" void kernel_launch(void* const* d_in, const int* in_sizes, int n_in,
                              void* d_out, int out_size)
{
    const float* x  = (const float*)d_in[0];
    const float* Wq = (const float*)d_in[1];
    const float* Wk = (const float*)d_in[2];
    const float* Wv = (const float*)d_in[3];
    const float* Wo = (const float*)d_in[4];
    const float* bo = (const float*)d_in[5];
    float* out = (float*)d_out;

    __half *qh, *kh, *kl, *vh, *vl, *x16, *ctx16;
    __half *wqh, *wql, *wkh, *wkl, *wvh, *wvl, *woh, *wol;
    cudaGetSymbolAddress((void**)&qh,    g_qh);
    cudaGetSymbolAddress((void**)&kh,    g_kh);
    cudaGetSymbolAddress((void**)&kl,    g_kl);
    cudaGetSymbolAddress((void**)&vh,    g_vh);
    cudaGetSymbolAddress((void**)&vl,    g_vl);
    cudaGetSymbolAddress((void**)&x16,   g_x16);
    cudaGetSymbolAddress((void**)&ctx16, g_ctx16);
    cudaGetSymbolAddress((void**)&wqh,   g_wqth);
    cudaGetSymbolAddress((void**)&wql,   g_wqtl);
    cudaGetSymbolAddress((void**)&wkh,   g_wkth);
    cudaGetSymbolAddress((void**)&wkl,   g_wktl);
    cudaGetSymbolAddress((void**)&wvh,   g_wvth);
    cudaGetSymbolAddress((void**)&wvl,   g_wvtl);
    cudaGetSymbolAddress((void**)&woh,   g_woth);
    cudaGetSymbolAddress((void**)&wol,   g_wotl);

    static bool attrs_set = false;
    if (!attrs_set) {
        cudaFuncSetAttribute(mma_gemm_kernel, cudaFuncAttributeMaxDynamicSharedMemorySize,
                             GEMM_SMEM);
        cudaFuncSetAttribute(attn4_kernel, cudaFuncAttributeMaxDynamicSharedMemorySize,
                             ATTN_SMEM);
        attrs_set = true;
    }

    dim3 blk(256);

    // conversions
    round_fp16_kernel<<<(MROWS * DIN / 4 + 255) / 256, blk>>>(x, x16, MROWS * DIN / 4);
    transpose_split_kernel<<<dim3(DOUT / 32, DIN / 32), blk>>>(Wq, wqh, wql, DIN, DOUT);
    transpose_split_kernel<<<dim3(KVDIM / 32, DIN / 32), blk>>>(Wk, wkh, wkl, DIN, KVDIM);
    transpose_split_kernel<<<dim3(KVDIM / 32, DIN / 32), blk>>>(Wv, wvh, wvl, DIN, KVDIM);
    transpose_split_kernel<<<dim3(DOUT / 32, DOUT / 32), blk>>>(Wo, woh, wol, DOUT, DOUT);

    // projections: q -> plain fp16; k,v -> exact hi/lo split
    mma_gemm_kernel<<<dim3(DOUT / 128, MROWS / 128), blk, GEMM_SMEM>>>(
        x16, wqh, wql, nullptr, qh, nullptr, nullptr, DOUT, DIN);
    mma_gemm_kernel<<<dim3(KVDIM / 128, MROWS / 128), blk, GEMM_SMEM>>>(
        x16, wkh, wkl, nullptr, kh, kl, nullptr, KVDIM, DIN);
    mma_gemm_kernel<<<dim3(KVDIM / 128, MROWS / 128), blk, GEMM_SMEM>>>(
        x16, wvh, wvl, nullptr, vh, vl, nullptr, KVDIM, DIN);

    // attention (plain fp16 ctx output)
    attn4_kernel<<<dim3(NSEQ / 64, NH, BSZ), dim3(128), ATTN_SMEM>>>(
        qh, kh, kl, vh, vl, ctx16);

    // output projection (fp32 + bias)
    mma_gemm_kernel<<<dim3(DOUT / 128, MROWS / 128), blk, GEMM_SMEM>>>(
        ctx16, woh, wol, out, nullptr, nullptr, bo, DOUT, DOUT);
}

// round 7
// speedup vs baseline: 10.0315x; 1.3966x over previous
#include <cuda_runtime.h>
#include <cuda_fp16.h>
#include <cstdint>
#include <cstddef>

// Problem constants
#define BSZ   2
#define NSEQ  2048
#define DIN   2048
#define DOUT  2048
#define NH    16
#define NG    4
#define HD    128
#define MROWS (BSZ * NSEQ)   // 4096
#define KVDIM (NG * HD)      // 512

// ---------------- scratch (no allocations allowed) ----------------
__device__ __align__(16) __half g_q16[MROWS * DOUT];
__device__ __align__(16) __half g_k16[MROWS * KVDIM];
__device__ __align__(16) __half g_v16[MROWS * KVDIM];
__device__ __align__(16) __half g_x16[MROWS * DIN];
__device__ __align__(16) __half g_ctx16[MROWS * DOUT];
__device__ __align__(16) __half g_wqt[DOUT * DIN];      // W^T [N,K] single
__device__ __align__(16) __half g_wkt[KVDIM * DIN];
__device__ __align__(16) __half g_wvt[KVDIM * DIN];
__device__ __align__(16) __half g_woth[DOUT * DOUT];    // Wo^T split hi/lo
__device__ __align__(16) __half g_wotl[DOUT * DOUT];

// ---------------- helpers ----------------
__device__ __forceinline__ uint32_t smem_u32(const void* p) {
    uint32_t a;
    asm("{ .reg .u64 t; cvta.to.shared.u64 t, %1; cvt.u32.u64 %0, t; }" : "=r"(a) : "l"(p));
    return a;
}
__device__ __forceinline__ void cp_async16(uint32_t saddr, const void* gaddr) {
    asm volatile("cp.async.cg.shared.global [%0], [%1], 16;" :: "r"(saddr), "l"(gaddr));
}
#define CP_COMMIT() asm volatile("cp.async.commit_group;" ::: "memory")
#define CP_WAIT(n)  asm volatile("cp.async.wait_group %0;" :: "n"(n) : "memory")

__device__ __forceinline__ void ldm_x4(uint32_t& r0, uint32_t& r1, uint32_t& r2, uint32_t& r3,
                                       uint32_t addr) {
    asm volatile("ldmatrix.sync.aligned.m8n8.x4.shared.b16 {%0, %1, %2, %3}, [%4];"
                 : "=r"(r0), "=r"(r1), "=r"(r2), "=r"(r3) : "r"(addr));
}
__device__ __forceinline__ void ldm_x4t(uint32_t& r0, uint32_t& r1, uint32_t& r2, uint32_t& r3,
                                        uint32_t addr) {
    asm volatile("ldmatrix.sync.aligned.m8n8.x4.trans.shared.b16 {%0, %1, %2, %3}, [%4];"
                 : "=r"(r0), "=r"(r1), "=r"(r2), "=r"(r3) : "r"(addr));
}
__device__ __forceinline__ void mma_f16(float* d, const uint32_t* a, const uint32_t* b) {
    asm volatile(
        "mma.sync.aligned.m16n8k16.row.col.f32.f16.f16.f32 "
        "{%0, %1, %2, %3}, {%4, %5, %6, %7}, {%8, %9}, {%0, %1, %2, %3};"
        : "+f"(d[0]), "+f"(d[1]), "+f"(d[2]), "+f"(d[3])
        : "r"(a[0]), "r"(a[1]), "r"(a[2]), "r"(a[3]), "r"(b[0]), "r"(b[1]));
}
__device__ __forceinline__ uint32_t pack_half2(float a, float b) {
    __half2 h = __halves2half2(__float2half_rn(a), __float2half_rn(b));
    return *reinterpret_cast<uint32_t*>(&h);
}

// ---------------- conversion kernels ----------------
__global__ __launch_bounds__(256) void round_fp16_kernel(
    const float* __restrict__ in, __half* __restrict__ out, int n4)
{
    int i = blockIdx.x * 256 + threadIdx.x;
    if (i >= n4) return;
    float4 v = ((const float4*)in)[i];
    ((__half2*)out)[2 * i]     = __halves2half2(__float2half_rn(v.x), __float2half_rn(v.y));
    ((__half2*)out)[2 * i + 1] = __halves2half2(__float2half_rn(v.z), __float2half_rn(v.w));
}

// W[K,N] fp32 -> T[N,K] fp16 single
__global__ __launch_bounds__(256) void transpose_single_kernel(
    const float* __restrict__ W, __half* __restrict__ T, int K, int N)
{
    __shared__ float tile[32][33];
    int k0 = blockIdx.y * 32, n0 = blockIdx.x * 32;
    int tx = threadIdx.x & 31, ty = threadIdx.x >> 5;
    #pragma unroll
    for (int r = ty; r < 32; r += 8)
        tile[r][tx] = W[(size_t)(k0 + r) * N + n0 + tx];
    __syncthreads();
    #pragma unroll
    for (int r = ty; r < 32; r += 8)
        T[(size_t)(n0 + r) * K + k0 + tx] = __float2half_rn(tile[tx][r]);
}

// W[K,N] fp32 -> T[N,K] fp16 hi/lo (exact split)
__global__ __launch_bounds__(256) void transpose_split_kernel(
    const float* __restrict__ W, __half* __restrict__ Th,
    __half* __restrict__ Tl, int K, int N)
{
    __shared__ float tile[32][33];
    int k0 = blockIdx.y * 32, n0 = blockIdx.x * 32;
    int tx = threadIdx.x & 31, ty = threadIdx.x >> 5;
    #pragma unroll
    for (int r = ty; r < 32; r += 8)
        tile[r][tx] = W[(size_t)(k0 + r) * N + n0 + tx];
    __syncthreads();
    #pragma unroll
    for (int r = ty; r < 32; r += 8) {
        float v = tile[tx][r];
        __half h = __float2half_rn(v);
        __half l = __float2half_rn(v - __half2float(h));
        size_t o = (size_t)(n0 + r) * K + k0 + tx;
        Th[o] = h;
        Tl[o] = l;
    }
}

// ---------------- HMMA GEMM: C = A[M,K] @ B[N,K]^T (B optionally split) ----------------
// CTA 128x128, BK=32, 8 warps (2M x 4N). Rows padded to 40 halfs.
#define GBK       32
#define LDROW     40
#define TILE_B    (128 * LDROW * 2)        // 10240 B
#define STAGE_B   (3 * TILE_B)             // 30720 B (A, Bh, [Bl])
#define GEMM_SMEM (2 * STAGE_B)            // 61440 B

__global__ __launch_bounds__(256, 2) void mma_gemm_kernel(
    const __half* __restrict__ A,
    const __half* __restrict__ Bh, const __half* __restrict__ Bl,
    float* __restrict__ C, __half* __restrict__ Chf,
    const float* __restrict__ bias, int N, int K)
{
    extern __shared__ char smem[];
    const uint32_t sb = smem_u32(smem);
    const int tid  = threadIdx.x;
    const int wid  = tid >> 5;
    const int lane = tid & 31;
    const int row0 = blockIdx.y * 128;
    const int col0 = blockIdx.x * 128;
    const int wm   = (wid & 1) * 64;
    const int wn   = (wid >> 1) * 32;
    const bool has_bl = (Bl != nullptr);

    float acc[4][4][4];
    #pragma unroll
    for (int i = 0; i < 4; i++)
        #pragma unroll
        for (int j = 0; j < 4; j++)
            #pragma unroll
            for (int r = 0; r < 4; r++) acc[i][j][r] = 0.f;

    const int nch = K / GBK;

    auto load_one = [&](const __half* src, int grow0, int tensor, int k0, uint32_t sbase) {
        #pragma unroll
        for (int t = 0; t < 2; t++) {
            int idx = tid + t * 256;            // 0..511
            int r = idx >> 2;
            int c = idx & 3;
            const __half* gp = src + (size_t)(grow0 + r) * K + k0 + c * 8;
            cp_async16(sbase + tensor * TILE_B + (r * LDROW + c * 8) * 2, gp);
        }
    };
    auto load_stage = [&](int ch, int stage) {
        const int k0 = ch * GBK;
        const uint32_t sbase = sb + stage * STAGE_B;
        load_one(A, row0, 0, k0, sbase);
        load_one(Bh, col0, 1, k0, sbase);
        if (has_bl) load_one(Bl, col0, 2, k0, sbase);
    };

    load_stage(0, 0);
    CP_COMMIT();

    for (int ch = 0; ch < nch; ch++) {
        if (ch + 1 < nch) {
            load_stage(ch + 1, (ch + 1) & 1);
            CP_COMMIT();
            CP_WAIT(1);
        } else {
            CP_WAIT(0);
        }
        __syncthreads();

        const uint32_t sbase = sb + (ch & 1) * STAGE_B;
        const uint32_t a_t  = sbase + 0 * TILE_B;
        const uint32_t b_hi = sbase + 1 * TILE_B;
        const uint32_t b_lo = sbase + 2 * TILE_B;

        #pragma unroll
        for (int ks = 0; ks < 2; ks++) {
            const uint32_t kb = ks * 32;
            uint32_t fa[4][4];
            #pragma unroll
            for (int mi = 0; mi < 4; mi++) {
                uint32_t roff = (uint32_t)(wm + mi * 16 + (lane & 15)) * (LDROW * 2)
                              + kb + (lane >> 4) * 16;
                ldm_x4(fa[mi][0], fa[mi][1], fa[mi][2], fa[mi][3], a_t + roff);
            }
            uint32_t fbh[4][2];
            #pragma unroll
            for (int p = 0; p < 2; p++) {
                uint32_t roff = (uint32_t)(wn + p * 16 + (lane >> 4) * 8 + (lane & 7)) * (LDROW * 2)
                              + kb + ((lane >> 3) & 1) * 16;
                uint32_t r0, r1, r2, r3;
                ldm_x4(r0, r1, r2, r3, b_hi + roff);
                fbh[2 * p][0] = r0; fbh[2 * p][1] = r1;
                fbh[2 * p + 1][0] = r2; fbh[2 * p + 1][1] = r3;
            }
            #pragma unroll
            for (int mi = 0; mi < 4; mi++)
                #pragma unroll
                for (int ni = 0; ni < 4; ni++)
                    mma_f16(acc[mi][ni], fa[mi], fbh[ni]);

            if (has_bl) {
                uint32_t fbl[4][2];
                #pragma unroll
                for (int p = 0; p < 2; p++) {
                    uint32_t roff = (uint32_t)(wn + p * 16 + (lane >> 4) * 8 + (lane & 7)) * (LDROW * 2)
                                  + kb + ((lane >> 3) & 1) * 16;
                    uint32_t r0, r1, r2, r3;
                    ldm_x4(r0, r1, r2, r3, b_lo + roff);
                    fbl[2 * p][0] = r0; fbl[2 * p][1] = r1;
                    fbl[2 * p + 1][0] = r2; fbl[2 * p + 1][1] = r3;
                }
                #pragma unroll
                for (int mi = 0; mi < 4; mi++)
                    #pragma unroll
                    for (int ni = 0; ni < 4; ni++)
                        mma_f16(acc[mi][ni], fa[mi], fbl[ni]);
            }
        }
        __syncthreads();
    }

    const int qrow = lane >> 2;
    const int qcol = (lane & 3) * 2;
    #pragma unroll
    for (int mi = 0; mi < 4; mi++) {
        #pragma unroll
        for (int ni = 0; ni < 4; ni++) {
            int r = row0 + wm + mi * 16 + qrow;
            int c = col0 + wn + ni * 8 + qcol;
            if (C != nullptr) {
                float b0 = 0.f, b1 = 0.f;
                if (bias != nullptr) { b0 = bias[c]; b1 = bias[c + 1]; }
                *(float2*)(C + (size_t)r * N + c) =
                    make_float2(acc[mi][ni][0] + b0, acc[mi][ni][1] + b1);
                *(float2*)(C + (size_t)(r + 8) * N + c) =
                    make_float2(acc[mi][ni][2] + b0, acc[mi][ni][3] + b1);
            } else {
                *(uint32_t*)(Chf + (size_t)r * N + c) =
                    pack_half2(acc[mi][ni][0], acc[mi][ni][1]);
                *(uint32_t*)(Chf + (size_t)(r + 8) * N + c) =
                    pack_half2(acc[mi][ni][2], acc[mi][ni][3]);
            }
        }
    }
}

// ---------------- HMMA fp16 causal GQA flash attention (single-pass) ----------------
// CTA: (b,h) x 64 query rows; 4 warps x 16 rows; key blocks of 64.
#define AROWB 136                          // halfs per padded row (272 B)
#define ATILE (64 * AROWB * 2)             // 17408 B
#define ATTN_SMEM (3 * ATILE)              // 52224 B

__global__ __launch_bounds__(128, 2) void attn5_kernel(
    const __half* __restrict__ Q,
    const __half* __restrict__ K16,
    const __half* __restrict__ V16,
    __half* __restrict__ Cx)
{
    extern __shared__ char smem[];
    const uint32_t sb = smem_u32(smem);
    const int tid  = threadIdx.x;
    const int wid  = tid >> 5;
    const int lane = tid & 31;
    const int b = blockIdx.z;
    const int h = blockIdx.y;
    const int g = h >> 2;
    const int qb = gridDim.x - 1 - blockIdx.x;
    const int q0 = qb * 64;
    const int wrow = wid * 16;

    const uint32_t s_q = sb + 0 * ATILE;
    const uint32_t s_k = sb + 1 * ATILE;
    const uint32_t s_v = sb + 2 * ATILE;

    const float scale = 0.08838834764831845f;

    // load Q tile (64 x 128 halfs)
    #pragma unroll
    for (int t = 0; t < 8; t++) {
        int idx = tid + t * 128;
        int r = idx >> 4;
        int c = idx & 15;
        size_t go = ((size_t)(b * NSEQ + q0 + r) * NH + h) * HD + c * 8;
        cp_async16(s_q + (uint32_t)r * (AROWB * 2) + c * 16, Q + go);
    }
    CP_COMMIT();

    float m0 = -1e30f, m1 = -1e30f, l0 = 0.f, l1 = 0.f;
    float o[16][4];
    #pragma unroll
    for (int n = 0; n < 16; n++)
        #pragma unroll
        for (int r = 0; r < 4; r++) o[n][r] = 0.f;

    for (int kb = 0; kb <= qb; kb++) {
        __syncthreads();
        #pragma unroll
        for (int t = 0; t < 8; t++) {
            int idx = tid + t * 128;
            int r = idx >> 4;
            int c = idx & 15;
            size_t go = ((size_t)(b * NSEQ + kb * 64 + r) * NG + g) * HD + c * 8;
            uint32_t so = (uint32_t)r * (AROWB * 2) + c * 16;
            cp_async16(s_k + so, K16 + go);
            cp_async16(s_v + so, V16 + go);
        }
        CP_COMMIT();
        CP_WAIT(0);
        __syncthreads();

        // ---- scores: S[16 x 64] = Q @ K^T ----
        float sacc[8][4];
        #pragma unroll
        for (int j = 0; j < 8; j++)
            #pragma unroll
            for (int r = 0; r < 4; r++) sacc[j][r] = 0.f;

        #pragma unroll
        for (int kc = 0; kc < 8; kc++) {
            uint32_t aoff = (uint32_t)(wrow + (lane & 15)) * (AROWB * 2)
                          + kc * 32 + (lane >> 4) * 16;
            uint32_t fa[4];
            ldm_x4(fa[0], fa[1], fa[2], fa[3], s_q + aoff);
            uint32_t fb[8][2];
            #pragma unroll
            for (int p = 0; p < 4; p++) {
                uint32_t boff = (uint32_t)(p * 16 + (lane >> 4) * 8 + (lane & 7)) * (AROWB * 2)
                              + kc * 32 + ((lane >> 3) & 1) * 16;
                uint32_t r0, r1, r2, r3;
                ldm_x4(r0, r1, r2, r3, s_k + boff);
                fb[2 * p][0] = r0; fb[2 * p][1] = r1;
                fb[2 * p + 1][0] = r2; fb[2 * p + 1][1] = r3;
            }
            #pragma unroll
            for (int j = 0; j < 8; j++)
                mma_f16(sacc[j], fa, fb[j]);
        }

        // ---- scale + causal mask + row stats ----
        const bool diag = (kb == qb);
        const int qr0 = q0 + wrow + (lane >> 2);
        float mb0 = -1e30f, mb1 = -1e30f;
        #pragma unroll
        for (int j = 0; j < 8; j++) {
            #pragma unroll
            for (int r = 0; r < 4; r++) sacc[j][r] *= scale;
            if (diag) {
                int key = kb * 64 + j * 8 + (lane & 3) * 2;
                if (key     > qr0)     sacc[j][0] = -1e30f;
                if (key + 1 > qr0)     sacc[j][1] = -1e30f;
                if (key     > qr0 + 8) sacc[j][2] = -1e30f;
                if (key + 1 > qr0 + 8) sacc[j][3] = -1e30f;
            }
            mb0 = fmaxf(mb0, fmaxf(sacc[j][0], sacc[j][1]));
            mb1 = fmaxf(mb1, fmaxf(sacc[j][2], sacc[j][3]));
        }
        mb0 = fmaxf(mb0, __shfl_xor_sync(0xFFFFFFFFu, mb0, 1));
        mb0 = fmaxf(mb0, __shfl_xor_sync(0xFFFFFFFFu, mb0, 2));
        mb1 = fmaxf(mb1, __shfl_xor_sync(0xFFFFFFFFu, mb1, 1));
        mb1 = fmaxf(mb1, __shfl_xor_sync(0xFFFFFFFFu, mb1, 2));

        float mn0 = fmaxf(m0, mb0), mn1 = fmaxf(m1, mb1);
        float a0 = __expf(m0 - mn0), a1 = __expf(m1 - mn1);
        m0 = mn0; m1 = mn1;

        // ---- exp + pack P as fp16 A-fragments ----
        float s0 = 0.f, s1 = 0.f;
        uint32_t pa[4][4];
        #pragma unroll
        for (int j = 0; j < 8; j++) {
            float p0 = __expf(sacc[j][0] - mn0);
            float p1 = __expf(sacc[j][1] - mn0);
            float p2 = __expf(sacc[j][2] - mn1);
            float p3 = __expf(sacc[j][3] - mn1);
            s0 += p0 + p1;
            s1 += p2 + p3;
            int t = j >> 1, w = (j & 1) * 2;
            pa[t][0 + w] = pack_half2(p0, p1);
            pa[t][1 + w] = pack_half2(p2, p3);
        }
        s0 += __shfl_xor_sync(0xFFFFFFFFu, s0, 1);
        s0 += __shfl_xor_sync(0xFFFFFFFFu, s0, 2);
        s1 += __shfl_xor_sync(0xFFFFFFFFu, s1, 1);
        s1 += __shfl_xor_sync(0xFFFFFFFFu, s1, 2);
        l0 = l0 * a0 + s0;
        l1 = l1 * a1 + s1;

        #pragma unroll
        for (int n = 0; n < 16; n++) {
            o[n][0] *= a0; o[n][1] *= a0;
            o[n][2] *= a1; o[n][3] *= a1;
        }

        // ---- PV: O[16 x 128] += P @ V ----
        #pragma unroll
        for (int np = 0; np < 8; np++) {
            #pragma unroll
            for (int t = 0; t < 4; t++) {
                uint32_t vaddr = (uint32_t)(16 * t + (lane & 7) + ((lane >> 3) & 1) * 8) * (AROWB * 2)
                               + (np * 16 + (lane >> 4) * 8) * 2;
                uint32_t h0, h1, h2, h3;
                ldm_x4t(h0, h1, h2, h3, s_v + vaddr);
                uint32_t bh0[2] = {h0, h1}, bh1[2] = {h2, h3};
                mma_f16(o[2 * np],     pa[t], bh0);
                mma_f16(o[2 * np + 1], pa[t], bh1);
            }
        }
    }

    // ---- epilogue: normalize, store ctx fp16 ----
    const float inv0 = 1.f / l0, inv1 = 1.f / l1;
    const int r0g = q0 + wrow + (lane >> 2);
    const int r1g = r0g + 8;
    #pragma unroll
    for (int n = 0; n < 16; n++) {
        int d = n * 8 + (lane & 3) * 2;
        size_t off0 = ((size_t)(b * NSEQ + r0g) * NH + h) * HD + d;
        size_t off1 = ((size_t)(b * NSEQ + r1g) * NH + h) * HD + d;
        *(uint32_t*)(Cx + off0) = pack_half2(o[n][0] * inv0, o[n][1] * inv0);
        *(uint32_t*)(Cx + off1) = pack_half2(o[n][2] * inv1, o[n][3] * inv1);
    }
}

// ---------------- launch ----------------
extern "C" void kernel_launch(void* const* d_in, const int* in_sizes, int n_in,
                              void* d_out, int out_size)
{
    const float* x  = (const float*)d_in[0];
    const float* Wq = (const float*)d_in[1];
    const float* Wk = (const float*)d_in[2];
    const float* Wv = (const float*)d_in[3];
    const float* Wo = (const float*)d_in[4];
    const float* bo = (const float*)d_in[5];
    float* out = (float*)d_out;

    __half *q16, *k16, *v16, *x16, *ctx16, *wqt, *wkt, *wvt, *woh, *wol;
    cudaGetSymbolAddress((void**)&q16,   g_q16);
    cudaGetSymbolAddress((void**)&k16,   g_k16);
    cudaGetSymbolAddress((void**)&v16,   g_v16);
    cudaGetSymbolAddress((void**)&x16,   g_x16);
    cudaGetSymbolAddress((void**)&ctx16, g_ctx16);
    cudaGetSymbolAddress((void**)&wqt,   g_wqt);
    cudaGetSymbolAddress((void**)&wkt,   g_wkt);
    cudaGetSymbolAddress((void**)&wvt,   g_wvt);
    cudaGetSymbolAddress((void**)&woh,   g_woth);
    cudaGetSymbolAddress((void**)&wol,   g_wotl);

    static bool attrs_set = false;
    if (!attrs_set) {
        cudaFuncSetAttribute(mma_gemm_kernel, cudaFuncAttributeMaxDynamicSharedMemorySize,
                             GEMM_SMEM);
        cudaFuncSetAttribute(attn5_kernel, cudaFuncAttributeMaxDynamicSharedMemorySize,
                             ATTN_SMEM);
        attrs_set = true;
    }

    dim3 blk(256);

    // conversions
    round_fp16_kernel<<<(MROWS * DIN / 4 + 255) / 256, blk>>>(x, x16, MROWS * DIN / 4);
    transpose_single_kernel<<<dim3(DOUT / 32, DIN / 32), blk>>>(Wq, wqt, DIN, DOUT);
    transpose_single_kernel<<<dim3(KVDIM / 32, DIN / 32), blk>>>(Wk, wkt, DIN, KVDIM);
    transpose_single_kernel<<<dim3(KVDIM / 32, DIN / 32), blk>>>(Wv, wvt, DIN, KVDIM);
    transpose_split_kernel<<<dim3(DOUT / 32, DOUT / 32), blk>>>(Wo, woh, wol, DOUT, DOUT);

    // projections (1-pass, fp16 outputs)
    mma_gemm_kernel<<<dim3(DOUT / 128, MROWS / 128), blk, GEMM_SMEM>>>(
        x16, wqt, nullptr, nullptr, q16, nullptr, DOUT, DIN);
    mma_gemm_kernel<<<dim3(KVDIM / 128, MROWS / 128), blk, GEMM_SMEM>>>(
        x16, wkt, nullptr, nullptr, k16, nullptr, KVDIM, DIN);
    mma_gemm_kernel<<<dim3(KVDIM / 128, MROWS / 128), blk, GEMM_SMEM>>>(
        x16, wvt, nullptr, nullptr, v16, nullptr, KVDIM, DIN);

    // attention (fp16 ctx output)
    attn5_kernel<<<dim3(NSEQ / 64, NH, BSZ), dim3(128), ATTN_SMEM>>>(
        q16, k16, v16, ctx16);

    // output projection (2-pass split Wo, fp32 + bias)
    mma_gemm_kernel<<<dim3(DOUT / 128, MROWS / 128), blk, GEMM_SMEM>>>(
        ctx16, woh, wol, out, nullptr, bo, DOUT, DOUT);
}

// round 8
// speedup vs baseline: 13.1676x; 1.3126x over previous
#include <cuda_runtime.h>
#include <cuda_fp16.h>
#include <cstdint>
#include <cstddef>

// Problem constants
#define BSZ   2
#define NSEQ  2048
#define DIN   2048
#define DOUT  2048
#define NH    16
#define NG    4
#define HD    128
#define MROWS (BSZ * NSEQ)   // 4096
#define KVDIM (NG * HD)      // 512
#define NQKV  (DOUT + 2 * KVDIM)   // 3072

// ---------------- scratch (no allocations allowed) ----------------
__device__ __align__(16) __half g_q16[MROWS * DOUT];
__device__ __align__(16) __half g_k16[MROWS * KVDIM];
__device__ __align__(16) __half g_v16[MROWS * KVDIM];
__device__ __align__(16) __half g_x16[MROWS * DIN];
__device__ __align__(16) __half g_ctx16[MROWS * DOUT];
__device__ __align__(16) __half g_wqkvt[NQKV * DIN];    // [Wq;Wk;Wv]^T rows 0..3071
__device__ __align__(16) __half g_wot[DOUT * DOUT];     // Wo^T single

// ---------------- helpers ----------------
__device__ __forceinline__ uint32_t smem_u32(const void* p) {
    uint32_t a;
    asm("{ .reg .u64 t; cvta.to.shared.u64 t, %1; cvt.u32.u64 %0, t; }" : "=r"(a) : "l"(p));
    return a;
}
__device__ __forceinline__ void cp_async16(uint32_t saddr, const void* gaddr) {
    asm volatile("cp.async.cg.shared.global [%0], [%1], 16;" :: "r"(saddr), "l"(gaddr));
}
#define CP_COMMIT() asm volatile("cp.async.commit_group;" ::: "memory")
#define CP_WAIT(n)  asm volatile("cp.async.wait_group %0;" :: "n"(n) : "memory")

__device__ __forceinline__ void ldm_x4(uint32_t& r0, uint32_t& r1, uint32_t& r2, uint32_t& r3,
                                       uint32_t addr) {
    asm volatile("ldmatrix.sync.aligned.m8n8.x4.shared.b16 {%0, %1, %2, %3}, [%4];"
                 : "=r"(r0), "=r"(r1), "=r"(r2), "=r"(r3) : "r"(addr));
}
__device__ __forceinline__ void ldm_x4t(uint32_t& r0, uint32_t& r1, uint32_t& r2, uint32_t& r3,
                                        uint32_t addr) {
    asm volatile("ldmatrix.sync.aligned.m8n8.x4.trans.shared.b16 {%0, %1, %2, %3}, [%4];"
                 : "=r"(r0), "=r"(r1), "=r"(r2), "=r"(r3) : "r"(addr));
}
__device__ __forceinline__ void mma_f16(float* d, const uint32_t* a, const uint32_t* b) {
    asm volatile(
        "mma.sync.aligned.m16n8k16.row.col.f32.f16.f16.f32 "
        "{%0, %1, %2, %3}, {%4, %5, %6, %7}, {%8, %9}, {%0, %1, %2, %3};"
        : "+f"(d[0]), "+f"(d[1]), "+f"(d[2]), "+f"(d[3])
        : "r"(a[0]), "r"(a[1]), "r"(a[2]), "r"(a[3]), "r"(b[0]), "r"(b[1]));
}
__device__ __forceinline__ uint32_t pack_half2(float a, float b) {
    __half2 h = __halves2half2(__float2half_rn(a), __float2half_rn(b));
    return *reinterpret_cast<uint32_t*>(&h);
}

// ---------------- conversion kernels ----------------
__global__ __launch_bounds__(256) void round_fp16_kernel(
    const float* __restrict__ in, __half* __restrict__ out, int n4)
{
    int i = blockIdx.x * 256 + threadIdx.x;
    if (i >= n4) return;
    float4 v = ((const float4*)in)[i];
    ((__half2*)out)[2 * i]     = __halves2half2(__float2half_rn(v.x), __float2half_rn(v.y));
    ((__half2*)out)[2 * i + 1] = __halves2half2(__float2half_rn(v.z), __float2half_rn(v.w));
}

// Fused transpose of Wq/Wk/Wv into g_wqkvt (rows: 0..2047 q, 2048..2559 k, 2560..3071 v)
__global__ __launch_bounds__(256) void transpose_qkv_kernel(
    const float* __restrict__ Wq, const float* __restrict__ Wk,
    const float* __restrict__ Wv, __half* __restrict__ T)
{
    __shared__ float tile[32][33];
    const int bx = blockIdx.x;          // 0..95
    const float* W;
    int n0, rowbase, Nsrc;
    if (bx < 64)      { W = Wq; n0 = bx * 32;        rowbase = 0;    Nsrc = DOUT; }
    else if (bx < 80) { W = Wk; n0 = (bx - 64) * 32; rowbase = 2048; Nsrc = KVDIM; }
    else              { W = Wv; n0 = (bx - 80) * 32; rowbase = 2560; Nsrc = KVDIM; }
    const int k0 = blockIdx.y * 32;
    const int tx = threadIdx.x & 31, ty = threadIdx.x >> 5;
    #pragma unroll
    for (int r = ty; r < 32; r += 8)
        tile[r][tx] = W[(size_t)(k0 + r) * Nsrc + n0 + tx];
    __syncthreads();
    #pragma unroll
    for (int r = ty; r < 32; r += 8)
        T[(size_t)(rowbase + n0 + r) * DIN + k0 + tx] = __float2half_rn(tile[tx][r]);
}

// W[K,N] fp32 -> T[N,K] fp16 single
__global__ __launch_bounds__(256) void transpose_single_kernel(
    const float* __restrict__ W, __half* __restrict__ T, int K, int N)
{
    __shared__ float tile[32][33];
    int k0 = blockIdx.y * 32, n0 = blockIdx.x * 32;
    int tx = threadIdx.x & 31, ty = threadIdx.x >> 5;
    #pragma unroll
    for (int r = ty; r < 32; r += 8)
        tile[r][tx] = W[(size_t)(k0 + r) * N + n0 + tx];
    __syncthreads();
    #pragma unroll
    for (int r = ty; r < 32; r += 8)
        T[(size_t)(n0 + r) * K + k0 + tx] = __float2half_rn(tile[tx][r]);
}

// ---------------- HMMA 1-pass GEMM: C = A[M,K] @ B[N,K]^T ----------------
// CTA 128x128, BK=32, 8 warps (2M x 4N), double-buffered cp.async.
// Epilogue: fp32+bias (C != null) or fp16 routed across q/k/v by column.
#define GBK       32
#define LDROW     40
#define TILE_B    (128 * LDROW * 2)        // 10240 B
#define STAGE_B   (2 * TILE_B)             // 20480 B (A, B)
#define GEMM_SMEM (2 * STAGE_B)            // 40960 B

__global__ __launch_bounds__(256, 2) void mma_gemm_kernel(
    const __half* __restrict__ A, const __half* __restrict__ B,
    float* __restrict__ C, const float* __restrict__ bias,
    __half* __restrict__ q16, __half* __restrict__ k16, __half* __restrict__ v16,
    int N, int K)
{
    extern __shared__ char smem[];
    const uint32_t sb = smem_u32(smem);
    const int tid  = threadIdx.x;
    const int wid  = tid >> 5;
    const int lane = tid & 31;
    const int row0 = blockIdx.y * 128;
    const int col0 = blockIdx.x * 128;
    const int wm   = (wid & 1) * 64;
    const int wn   = (wid >> 1) * 32;

    float acc[4][4][4];
    #pragma unroll
    for (int i = 0; i < 4; i++)
        #pragma unroll
        for (int j = 0; j < 4; j++)
            #pragma unroll
            for (int r = 0; r < 4; r++) acc[i][j][r] = 0.f;

    const int nch = K / GBK;

    auto load_stage = [&](int ch, int stage) {
        const int k0 = ch * GBK;
        const uint32_t sbase = sb + stage * STAGE_B;
        #pragma unroll
        for (int t = 0; t < 4; t++) {
            int idx = tid + t * 256;            // 0..1023
            int tensor = idx >> 9;              // 0 = A, 1 = B
            int rem = idx & 511;
            int r = rem >> 2;
            int c = rem & 3;
            const __half* gp = (tensor == 0)
                ? A + (size_t)(row0 + r) * K + k0 + c * 8
                : B + (size_t)(col0 + r) * K + k0 + c * 8;
            cp_async16(sbase + tensor * TILE_B + (r * LDROW + c * 8) * 2, gp);
        }
    };

    load_stage(0, 0);
    CP_COMMIT();

    for (int ch = 0; ch < nch; ch++) {
        if (ch + 1 < nch) {
            load_stage(ch + 1, (ch + 1) & 1);
            CP_COMMIT();
            CP_WAIT(1);
        } else {
            CP_WAIT(0);
        }
        __syncthreads();

        const uint32_t sbase = sb + (ch & 1) * STAGE_B;
        const uint32_t a_t = sbase;
        const uint32_t b_t = sbase + TILE_B;

        #pragma unroll
        for (int ks = 0; ks < 2; ks++) {
            const uint32_t kb = ks * 32;
            uint32_t fa[4][4];
            #pragma unroll
            for (int mi = 0; mi < 4; mi++) {
                uint32_t roff = (uint32_t)(wm + mi * 16 + (lane & 15)) * (LDROW * 2)
                              + kb + (lane >> 4) * 16;
                ldm_x4(fa[mi][0], fa[mi][1], fa[mi][2], fa[mi][3], a_t + roff);
            }
            uint32_t fb[4][2];
            #pragma unroll
            for (int p = 0; p < 2; p++) {
                uint32_t roff = (uint32_t)(wn + p * 16 + (lane >> 4) * 8 + (lane & 7)) * (LDROW * 2)
                              + kb + ((lane >> 3) & 1) * 16;
                uint32_t r0, r1, r2, r3;
                ldm_x4(r0, r1, r2, r3, b_t + roff);
                fb[2 * p][0] = r0; fb[2 * p][1] = r1;
                fb[2 * p + 1][0] = r2; fb[2 * p + 1][1] = r3;
            }
            #pragma unroll
            for (int mi = 0; mi < 4; mi++)
                #pragma unroll
                for (int ni = 0; ni < 4; ni++)
                    mma_f16(acc[mi][ni], fa[mi], fb[ni]);
        }
        __syncthreads();
    }

    const int qrow = lane >> 2;
    const int qcol = (lane & 3) * 2;
    if (C != nullptr) {
        #pragma unroll
        for (int mi = 0; mi < 4; mi++)
            #pragma unroll
            for (int ni = 0; ni < 4; ni++) {
                int r = row0 + wm + mi * 16 + qrow;
                int c = col0 + wn + ni * 8 + qcol;
                float b0 = 0.f, b1 = 0.f;
                if (bias != nullptr) { b0 = bias[c]; b1 = bias[c + 1]; }
                *(float2*)(C + (size_t)r * N + c) =
                    make_float2(acc[mi][ni][0] + b0, acc[mi][ni][1] + b1);
                *(float2*)(C + (size_t)(r + 8) * N + c) =
                    make_float2(acc[mi][ni][2] + b0, acc[mi][ni][3] + b1);
            }
    } else {
        // route by output column block (whole CTA maps to one tensor)
        __half* dst; int nD, c0;
        if (col0 < DOUT)              { dst = q16; nD = DOUT;  c0 = col0; }
        else if (col0 < DOUT + KVDIM) { dst = k16; nD = KVDIM; c0 = col0 - DOUT; }
        else                          { dst = v16; nD = KVDIM; c0 = col0 - DOUT - KVDIM; }
        #pragma unroll
        for (int mi = 0; mi < 4; mi++)
            #pragma unroll
            for (int ni = 0; ni < 4; ni++) {
                int r = row0 + wm + mi * 16 + qrow;
                int c = c0 + wn + ni * 8 + qcol;
                *(uint32_t*)(dst + (size_t)r * nD + c) =
                    pack_half2(acc[mi][ni][0], acc[mi][ni][1]);
                *(uint32_t*)(dst + (size_t)(r + 8) * nD + c) =
                    pack_half2(acc[mi][ni][2], acc[mi][ni][3]);
            }
    }
}

// ---------------- HMMA fp16 causal GQA flash attention (double-buffered K/V) ----------------
// CTA: (b,h) x 64 query rows; 4 warps x 16 rows; key blocks of 64.
#define AROWB 136                          // halfs per padded row (272 B)
#define ATILE (64 * AROWB * 2)             // 17408 B
#define ATTN_SMEM (5 * ATILE)              // 87040 B: Q, K0, V0, K1, V1

__global__ __launch_bounds__(128, 2) void attn6_kernel(
    const __half* __restrict__ Q,
    const __half* __restrict__ K16,
    const __half* __restrict__ V16,
    __half* __restrict__ Cx)
{
    extern __shared__ char smem[];
    const uint32_t sb = smem_u32(smem);
    const int tid  = threadIdx.x;
    const int wid  = tid >> 5;
    const int lane = tid & 31;
    const int b = blockIdx.z;
    const int h = blockIdx.y;
    const int g = h >> 2;
    const int qb = gridDim.x - 1 - blockIdx.x;
    const int q0 = qb * 64;
    const int wrow = wid * 16;

    const uint32_t s_q = sb;
    // buffers: [K0 V0][K1 V1]
    auto s_k = [&](int buf) { return sb + ATILE + buf * 2 * ATILE; };
    auto s_v = [&](int buf) { return sb + 2 * ATILE + buf * 2 * ATILE; };

    const float scale = 0.08838834764831845f;

    // load Q tile (group)
    #pragma unroll
    for (int t = 0; t < 8; t++) {
        int idx = tid + t * 128;
        int r = idx >> 4;
        int c = idx & 15;
        size_t go = ((size_t)(b * NSEQ + q0 + r) * NH + h) * HD + c * 8;
        cp_async16(s_q + (uint32_t)r * (AROWB * 2) + c * 16, Q + go);
    }
    CP_COMMIT();

    auto load_kv = [&](int kb, int buf) {
        #pragma unroll
        for (int t = 0; t < 8; t++) {
            int idx = tid + t * 128;
            int r = idx >> 4;
            int c = idx & 15;
            size_t go = ((size_t)(b * NSEQ + kb * 64 + r) * NG + g) * HD + c * 8;
            uint32_t so = (uint32_t)r * (AROWB * 2) + c * 16;
            cp_async16(s_k(buf) + so, K16 + go);
            cp_async16(s_v(buf) + so, V16 + go);
        }
        CP_COMMIT();
    };

    load_kv(0, 0);

    float m0 = -1e30f, m1 = -1e30f, l0 = 0.f, l1 = 0.f;
    float o[16][4];
    #pragma unroll
    for (int n = 0; n < 16; n++)
        #pragma unroll
        for (int r = 0; r < 4; r++) o[n][r] = 0.f;

    for (int kb = 0; kb <= qb; kb++) {
        const int cur = kb & 1;
        __syncthreads();                 // everyone done with buffer we're about to overwrite
        if (kb < qb) {
            load_kv(kb + 1, 1 - cur);
            CP_WAIT(1);
        } else {
            CP_WAIT(0);
        }
        __syncthreads();                 // cur buffer (and Q) visible to all

        const uint32_t sk = s_k(cur), sv = s_v(cur);

        // ---- scores: S[16 x 64] = Q @ K^T ----
        float sacc[8][4];
        #pragma unroll
        for (int j = 0; j < 8; j++)
            #pragma unroll
            for (int r = 0; r < 4; r++) sacc[j][r] = 0.f;

        #pragma unroll
        for (int kc = 0; kc < 8; kc++) {
            uint32_t aoff = (uint32_t)(wrow + (lane & 15)) * (AROWB * 2)
                          + kc * 32 + (lane >> 4) * 16;
            uint32_t fa[4];
            ldm_x4(fa[0], fa[1], fa[2], fa[3], s_q + aoff);
            uint32_t fb[8][2];
            #pragma unroll
            for (int p = 0; p < 4; p++) {
                uint32_t boff = (uint32_t)(p * 16 + (lane >> 4) * 8 + (lane & 7)) * (AROWB * 2)
                              + kc * 32 + ((lane >> 3) & 1) * 16;
                uint32_t r0, r1, r2, r3;
                ldm_x4(r0, r1, r2, r3, sk + boff);
                fb[2 * p][0] = r0; fb[2 * p][1] = r1;
                fb[2 * p + 1][0] = r2; fb[2 * p + 1][1] = r3;
            }
            #pragma unroll
            for (int j = 0; j < 8; j++)
                mma_f16(sacc[j], fa, fb[j]);
        }

        // ---- scale + causal mask + row stats ----
        const bool diag = (kb == qb);
        const int qr0 = q0 + wrow + (lane >> 2);
        float mb0 = -1e30f, mb1 = -1e30f;
        #pragma unroll
        for (int j = 0; j < 8; j++) {
            #pragma unroll
            for (int r = 0; r < 4; r++) sacc[j][r] *= scale;
            if (diag) {
                int key = kb * 64 + j * 8 + (lane & 3) * 2;
                if (key     > qr0)     sacc[j][0] = -1e30f;
                if (key + 1 > qr0)     sacc[j][1] = -1e30f;
                if (key     > qr0 + 8) sacc[j][2] = -1e30f;
                if (key + 1 > qr0 + 8) sacc[j][3] = -1e30f;
            }
            mb0 = fmaxf(mb0, fmaxf(sacc[j][0], sacc[j][1]));
            mb1 = fmaxf(mb1, fmaxf(sacc[j][2], sacc[j][3]));
        }
        mb0 = fmaxf(mb0, __shfl_xor_sync(0xFFFFFFFFu, mb0, 1));
        mb0 = fmaxf(mb0, __shfl_xor_sync(0xFFFFFFFFu, mb0, 2));
        mb1 = fmaxf(mb1, __shfl_xor_sync(0xFFFFFFFFu, mb1, 1));
        mb1 = fmaxf(mb1, __shfl_xor_sync(0xFFFFFFFFu, mb1, 2));

        float mn0 = fmaxf(m0, mb0), mn1 = fmaxf(m1, mb1);
        float a0 = __expf(m0 - mn0), a1 = __expf(m1 - mn1);
        m0 = mn0; m1 = mn1;

        // ---- exp + pack P as fp16 A-fragments ----
        float s0 = 0.f, s1 = 0.f;
        uint32_t pa[4][4];
        #pragma unroll
        for (int j = 0; j < 8; j++) {
            float p0 = __expf(sacc[j][0] - mn0);
            float p1 = __expf(sacc[j][1] - mn0);
            float p2 = __expf(sacc[j][2] - mn1);
            float p3 = __expf(sacc[j][3] - mn1);
            s0 += p0 + p1;
            s1 += p2 + p3;
            int t = j >> 1, w = (j & 1) * 2;
            pa[t][0 + w] = pack_half2(p0, p1);
            pa[t][1 + w] = pack_half2(p2, p3);
        }
        s0 += __shfl_xor_sync(0xFFFFFFFFu, s0, 1);
        s0 += __shfl_xor_sync(0xFFFFFFFFu, s0, 2);
        s1 += __shfl_xor_sync(0xFFFFFFFFu, s1, 1);
        s1 += __shfl_xor_sync(0xFFFFFFFFu, s1, 2);
        l0 = l0 * a0 + s0;
        l1 = l1 * a1 + s1;

        #pragma unroll
        for (int n = 0; n < 16; n++) {
            o[n][0] *= a0; o[n][1] *= a0;
            o[n][2] *= a1; o[n][3] *= a1;
        }

        // ---- PV: O[16 x 128] += P @ V ----
        #pragma unroll
        for (int np = 0; np < 8; np++) {
            #pragma unroll
            for (int t = 0; t < 4; t++) {
                uint32_t vaddr = (uint32_t)(16 * t + (lane & 7) + ((lane >> 3) & 1) * 8) * (AROWB * 2)
                               + (np * 16 + (lane >> 4) * 8) * 2;
                uint32_t h0, h1, h2, h3;
                ldm_x4t(h0, h1, h2, h3, sv + vaddr);
                uint32_t bh0[2] = {h0, h1}, bh1[2] = {h2, h3};
                mma_f16(o[2 * np],     pa[t], bh0);
                mma_f16(o[2 * np + 1], pa[t], bh1);
            }
        }
    }

    // ---- epilogue: normalize, store ctx fp16 ----
    const float inv0 = 1.f / l0, inv1 = 1.f / l1;
    const int r0g = q0 + wrow + (lane >> 2);
    const int r1g = r0g + 8;
    #pragma unroll
    for (int n = 0; n < 16; n++) {
        int d = n * 8 + (lane & 3) * 2;
        size_t off0 = ((size_t)(b * NSEQ + r0g) * NH + h) * HD + d;
        size_t off1 = ((size_t)(b * NSEQ + r1g) * NH + h) * HD + d;
        *(uint32_t*)(Cx + off0) = pack_half2(o[n][0] * inv0, o[n][1] * inv0);
        *(uint32_t*)(Cx + off1) = pack_half2(o[n][2] * inv1, o[n][3] * inv1);
    }
}

// ---------------- launch ----------------
extern "C" void kernel_launch(void* const* d_in, const int* in_sizes, int n_in,
                              void* d_out, int out_size)
{
    const float* x  = (const float*)d_in[0];
    const float* Wq = (const float*)d_in[1];
    const float* Wk = (const float*)d_in[2];
    const float* Wv = (const float*)d_in[3];
    const float* Wo = (const float*)d_in[4];
    const float* bo = (const float*)d_in[5];
    float* out = (float*)d_out;

    __half *q16, *k16, *v16, *x16, *ctx16, *wqkvt, *wot;
    cudaGetSymbolAddress((void**)&q16,   g_q16);
    cudaGetSymbolAddress((void**)&k16,   g_k16);
    cudaGetSymbolAddress((void**)&v16,   g_v16);
    cudaGetSymbolAddress((void**)&x16,   g_x16);
    cudaGetSymbolAddress((void**)&ctx16, g_ctx16);
    cudaGetSymbolAddress((void**)&wqkvt, g_wqkvt);
    cudaGetSymbolAddress((void**)&wot,   g_wot);

    static bool attrs_set = false;
    if (!attrs_set) {
        cudaFuncSetAttribute(mma_gemm_kernel, cudaFuncAttributeMaxDynamicSharedMemorySize,
                             GEMM_SMEM);
        cudaFuncSetAttribute(attn6_kernel, cudaFuncAttributeMaxDynamicSharedMemorySize,
                             ATTN_SMEM);
        attrs_set = true;
    }

    dim3 blk(256);

    // conversions
    round_fp16_kernel<<<(MROWS * DIN / 4 + 255) / 256, blk>>>(x, x16, MROWS * DIN / 4);
    transpose_qkv_kernel<<<dim3(96, DIN / 32), blk>>>(Wq, Wk, Wv, wqkvt);
    transpose_single_kernel<<<dim3(DOUT / 32, DOUT / 32), blk>>>(Wo, wot, DOUT, DOUT);

    // fused QKV projection (fp16 outputs, routed by column)
    mma_gemm_kernel<<<dim3(NQKV / 128, MROWS / 128), blk, GEMM_SMEM>>>(
        x16, wqkvt, nullptr, nullptr, q16, k16, v16, NQKV, DIN);

    // attention (fp16 ctx output)
    attn6_kernel<<<dim3(NSEQ / 64, NH, BSZ), dim3(128), ATTN_SMEM>>>(
        q16, k16, v16, ctx16);

    // output projection (1-pass, fp32 + bias)
    mma_gemm_kernel<<<dim3(DOUT / 128, MROWS / 128), blk, GEMM_SMEM>>>(
        ctx16, wot, out, bo, nullptr, nullptr, nullptr, DOUT, DOUT);
}